// round 1
// baseline (speedup 1.0000x reference)
#include <cuda_runtime.h>
#include <math.h>

#define NN 100000
#define EE 1600000
#define INC 32
#define HC  64
#define LC  16
#define GG  64

// ---- device scratch (static, no allocation) ----
__device__ float g_deg[NN];
__device__ float g_dinv[NN];
__device__ float g_xws[NN * HC];    // xw * dinv[src], per-conv scratch
__device__ float g_buf0[NN * HC];
__device__ float g_buf1[NN * HC];
__device__ float g_sums[GG * HC];
__device__ float g_cnt[GG];
__device__ float g_pool[GG * HC];
__device__ float g_z[GG * LC];

// ------------------------------------------------------------------
// degree / dinv
// ------------------------------------------------------------------
__global__ void k_zero() {
    int i = blockIdx.x * blockDim.x + threadIdx.x;
    if (i < NN) g_deg[i] = 0.f;
    if (i < GG * HC) g_sums[i] = 0.f;
    if (i < GG) g_cnt[i] = 0.f;
}

__global__ void k_count(const int* __restrict__ ei) {
    int e = blockIdx.x * blockDim.x + threadIdx.x;
    if (e < EE) atomicAdd(&g_deg[ei[EE + e]], 1.0f);
}

__global__ void k_dinv() {
    int i = blockIdx.x * blockDim.x + threadIdx.x;
    if (i < NN) g_dinv[i] = rsqrtf(g_deg[i] + 1.0f);
}

// ------------------------------------------------------------------
// GEMM + self-loop seed:  xws = (in@W)*dinv,  out = (in@W)*dinv^2 + b
// blockDim = 256. Each thread: one (node, channel).
// ------------------------------------------------------------------
template <int KIN, int COUT, bool RELUIN>
__global__ void k_gemm_self(const float* __restrict__ in,
                            const float* __restrict__ W,
                            const float* __restrict__ b,
                            float* __restrict__ xws,
                            float* __restrict__ out) {
    __shared__ float Ws[KIN * COUT];
    __shared__ float bs[COUT];
    const int tid = threadIdx.x;
    for (int i = tid; i < KIN * COUT; i += 256) Ws[i] = W[i];
    if (tid < COUT) bs[tid] = b[tid];
    __syncthreads();

    const int npb = 256 / COUT;
    const int n = blockIdx.x * npb + tid / COUT;
    const int c = tid % COUT;
    if (n >= NN) return;

    const float* xr = in + (long)n * KIN;
    float s = 0.f;
#pragma unroll
    for (int k = 0; k < KIN; k++) {
        float v = __ldg(&xr[k]);
        if (RELUIN) v = fmaxf(v, 0.f);
        s = fmaf(v, Ws[k * COUT + c], s);
    }
    const float d = g_dinv[n];
    const float sd = s * d;
    xws[(long)n * COUT + c] = sd;
    out[(long)n * COUT + c] = fmaf(sd, d, bs[c]);
}

// ------------------------------------------------------------------
// Edge scatter: out[dst] += xws[src] * dinv[dst]   (vector red, 16B)
// COUT/4 threads per edge.
// ------------------------------------------------------------------
template <int COUT>
__global__ void k_scatter(const int* __restrict__ ei,
                          const float* __restrict__ xws,
                          float* __restrict__ out) {
    const int TPE = COUT / 4;
    const int gid = blockIdx.x * blockDim.x + threadIdx.x;
    const int e = gid / TPE;
    const int t = gid % TPE;
    if (e >= EE) return;
    const int src = __ldg(&ei[e]);
    const int dst = __ldg(&ei[EE + e]);
    const float dd = __ldg(&g_dinv[dst]);
    const float4 v = *(const float4*)(xws + (long)src * COUT + t * 4);
    float* p = out + (long)dst * COUT + t * 4;
    asm volatile("red.global.add.v4.f32 [%0], {%1, %2, %3, %4};"
                 :: "l"(p), "f"(v.x * dd), "f"(v.y * dd), "f"(v.z * dd), "f"(v.w * dd)
                 : "memory");
}

// ------------------------------------------------------------------
// Global mean pool (smem-privatized), input relu'd on read
// blockDim = 256; c = tid%64, 4 nodes per block per iter
// ------------------------------------------------------------------
__global__ void k_pool(const int* __restrict__ batch, const float* __restrict__ h) {
    __shared__ float ss[GG * HC];
    __shared__ float sc[GG];
    const int tid = threadIdx.x;
    for (int i = tid; i < GG * HC; i += 256) ss[i] = 0.f;
    if (tid < GG) sc[tid] = 0.f;
    __syncthreads();

    const int c = tid % HC;
    const int r = tid / HC;
    for (int n = blockIdx.x * 4 + r; n < NN; n += gridDim.x * 4) {
        const int g = __ldg(&batch[n]);
        const float v = fmaxf(h[(long)n * HC + c], 0.f);
        atomicAdd(&ss[g * HC + c], v);
        if (c == 0) atomicAdd(&sc[g], 1.f);
    }
    __syncthreads();
    for (int i = tid; i < GG * HC; i += 256)
        if (ss[i] != 0.f) atomicAdd(&g_sums[i], ss[i]);
    if (tid < GG && sc[tid] != 0.f) atomicAdd(&g_cnt[tid], sc[tid]);
}

__global__ void k_pooldiv() {
    int i = blockIdx.x * blockDim.x + threadIdx.x;
    if (i < GG * HC) {
        int g = i / HC;
        g_pool[i] = g_sums[i] / fmaxf(g_cnt[g], 1.0f);
    }
}

// z = pool @ W_proj + b_proj  -> g_z and d_out tail. one block of 1024.
__global__ void k_zproj(const float* __restrict__ Wp, const float* __restrict__ bp,
                        float* __restrict__ zout) {
    const int tid = threadIdx.x;           // 0..1023
    const int g = tid / LC, l = tid % LC;
    float s = bp[l];
#pragma unroll
    for (int k = 0; k < HC; k++) s = fmaf(g_pool[g * HC + k], Wp[k * LC + l], s);
    g_z[g * LC + l] = s;
    zout[g * LC + l] = s;
}

// d = relu(z[batch] @ W_dec_proj + b)  -> out (stored relu'd)
__global__ void k_decproj(const int* __restrict__ batch,
                          const float* __restrict__ Wdp,
                          const float* __restrict__ bdp,
                          float* __restrict__ out) {
    __shared__ float zs[GG * LC];
    __shared__ float Ws[LC * HC];
    __shared__ float bs[HC];
    const int tid = threadIdx.x;
    for (int i = tid; i < GG * LC; i += 256) zs[i] = g_z[i];
    for (int i = tid; i < LC * HC; i += 256) Ws[i] = Wdp[i];
    if (tid < HC) bs[tid] = bdp[tid];
    __syncthreads();

    const int c = tid % HC;
    const int r = tid / HC;
    const int n = blockIdx.x * 4 + r;
    if (n >= NN) return;
    const int g = __ldg(&batch[n]);
    float s = bs[c];
#pragma unroll
    for (int k = 0; k < LC; k++) s = fmaf(zs[g * LC + k], Ws[k * HC + c], s);
    out[(long)n * HC + c] = fmaxf(s, 0.f);
}

// ------------------------------------------------------------------
extern "C" void kernel_launch(void* const* d_in, const int* in_sizes, int n_in,
                              void* d_out, int out_size) {
    const float* x       = (const float*)d_in[0];
    const int*   ei      = (const int*)  d_in[1];
    const int*   batch   = (const int*)  d_in[2];
    const float* W_enc0  = (const float*)d_in[3];
    const float* b_enc0  = (const float*)d_in[4];
    const float* W_enc1  = (const float*)d_in[5];
    const float* b_enc1  = (const float*)d_in[6];
    const float* W_enc2  = (const float*)d_in[7];
    const float* b_enc2  = (const float*)d_in[8];
    const float* W_proj  = (const float*)d_in[9];
    const float* b_proj  = (const float*)d_in[10];
    const float* W_decp  = (const float*)d_in[11];
    const float* b_decp  = (const float*)d_in[12];
    const float* W_dec0  = (const float*)d_in[13];
    const float* b_dec0  = (const float*)d_in[14];
    const float* W_dec1  = (const float*)d_in[15];
    const float* b_dec1  = (const float*)d_in[16];

    float* out  = (float*)d_out;
    float* xrec = out;             // [NN, INC]
    float* zout = out + NN * INC;  // [GG, LC]

    float *p_xws, *p_buf0, *p_buf1;
    cudaGetSymbolAddress((void**)&p_xws,  g_xws);
    cudaGetSymbolAddress((void**)&p_buf0, g_buf0);
    cudaGetSymbolAddress((void**)&p_buf1, g_buf1);

    const int TB = 256;
    const int gN   = (NN + TB - 1) / TB;
    const int gE   = (EE + TB - 1) / TB;
    const int gA64 = (NN + 3) / 4;          // k_gemm_self COUT=64
    const int gA32 = (NN + 7) / 8;          // k_gemm_self COUT=32
    const int gS64 = (EE * 16 + TB - 1) / TB;
    const int gS32 = (EE * 8  + TB - 1) / TB;

    // degree + dinv (+ zero pool accumulators)
    k_zero<<<gN, TB>>>();
    k_count<<<gE, TB>>>(ei);
    k_dinv<<<gN, TB>>>();

    // encoder conv0: x[N,32] -> buf0
    k_gemm_self<INC, HC, false><<<gA64, TB>>>(x, W_enc0, b_enc0, p_xws, p_buf0);
    k_scatter<HC><<<gS64, TB>>>(ei, p_xws, p_buf0);
    // conv1: relu(buf0) -> buf1
    k_gemm_self<HC, HC, true><<<gA64, TB>>>(p_buf0, W_enc1, b_enc1, p_xws, p_buf1);
    k_scatter<HC><<<gS64, TB>>>(ei, p_xws, p_buf1);
    // conv2: relu(buf1) -> buf0
    k_gemm_self<HC, HC, true><<<gA64, TB>>>(p_buf1, W_enc2, b_enc2, p_xws, p_buf0);
    k_scatter<HC><<<gS64, TB>>>(ei, p_xws, p_buf0);

    // pool relu(buf0) -> g_pool ; z
    k_pool<<<592, TB>>>(batch, p_buf0);
    k_pooldiv<<<(GG * HC + TB - 1) / TB, TB>>>();
    k_zproj<<<1, 1024>>>(W_proj, b_proj, zout);

    // decoder broadcast projection -> buf1 (relu'd)
    k_decproj<<<gA64, TB>>>(batch, W_decp, b_decp, p_buf1);
    // dec conv0: buf1 (already relu'd) -> buf0
    k_gemm_self<HC, HC, false><<<gA64, TB>>>(p_buf1, W_dec0, b_dec0, p_xws, p_buf0);
    k_scatter<HC><<<gS64, TB>>>(ei, p_xws, p_buf0);
    // dec conv1: relu(buf0) -> x_recon [N,32]
    k_gemm_self<HC, INC, true><<<gA32, TB>>>(p_buf0, W_dec1, b_dec1, p_xws, xrec);
    k_scatter<INC><<<gS32, TB>>>(ei, p_xws, xrec);
}

// round 2
// speedup vs baseline: 1.1833x; 1.1833x over previous
#include <cuda_runtime.h>
#include <math.h>

#define NN 100000
#define EE 1600000
#define INC 32
#define HC  64
#define LC  16
#define GG  64

// ---- device scratch (static, no allocation) ----
__device__ float g_deg[NN];
__device__ float g_dinv[NN];
__device__ float g_xws[NN * HC];    // xw * dinv[src], per-conv scratch
__device__ float g_buf0[NN * HC];
__device__ float g_buf1[NN * HC];
__device__ float g_sums[GG * HC];
__device__ float g_cnt[GG];
__device__ float g_pool[GG * HC];
__device__ float g_z[GG * LC];

// ------------------------------------------------------------------
// degree / dinv
// ------------------------------------------------------------------
__global__ void k_zero() {
    int i = blockIdx.x * blockDim.x + threadIdx.x;
    if (i < NN) g_deg[i] = 0.f;
    if (i < GG * HC) g_sums[i] = 0.f;
    if (i < GG) g_cnt[i] = 0.f;
}

__global__ void k_count(const int* __restrict__ ei) {
    int e = blockIdx.x * blockDim.x + threadIdx.x;
    if (e < EE) atomicAdd(&g_deg[ei[EE + e]], 1.0f);
}

__global__ void k_dinv() {
    int i = blockIdx.x * blockDim.x + threadIdx.x;
    if (i < NN) g_dinv[i] = rsqrtf(g_deg[i] + 1.0f);
}

// ------------------------------------------------------------------
// GEMM + self-loop seed:  xws = (in@W)*dinv,  out = (in@W)*dinv^2 + b
// Register-blocked: 8 channels per thread, input rows staged in smem
// (relu folded at stage), W via float4 LDS. blockDim = 256.
// ------------------------------------------------------------------
template <int KIN, int COUT, bool RELUIN>
__global__ void k_gemm_self(const float* __restrict__ in,
                            const float* __restrict__ W,
                            const float* __restrict__ b,
                            float* __restrict__ xws,
                            float* __restrict__ out) {
    constexpr int CPT = 8;            // channels per thread
    constexpr int TPN = COUT / CPT;   // threads per node (8 or 4)
    constexpr int NPB = 256 / TPN;    // nodes per block (32 or 64)
    constexpr int XSS = KIN + 4;      // padded smem stride (bank-spread)

    __shared__ float Ws[KIN * COUT];
    __shared__ float bs[COUT];
    __shared__ float xs[NPB * XSS];

    const int tid = threadIdx.x;
    const int n0 = blockIdx.x * NPB;

    // stage W (float4, counts divide evenly: 2048 or 4096 floats)
    {
        const float4* W4 = (const float4*)W;
        float4* Ws4 = (float4*)Ws;
#pragma unroll
        for (int i = tid; i < KIN * COUT / 4; i += 256) Ws4[i] = W4[i];
    }
    if (tid < COUT) bs[tid] = b[tid];

    // stage input rows (relu folded)
    {
        const int nquads = NPB * KIN / 4;
        for (int i = tid; i < nquads; i += 256) {
            const int row = (i * 4) / KIN;
            const int col = (i * 4) % KIN;
            float4 v;
            if (n0 + row < NN) {
                v = *(const float4*)(in + (long)(n0 + row) * KIN + col);
                if (RELUIN) {
                    v.x = fmaxf(v.x, 0.f); v.y = fmaxf(v.y, 0.f);
                    v.z = fmaxf(v.z, 0.f); v.w = fmaxf(v.w, 0.f);
                }
            } else {
                v = make_float4(0.f, 0.f, 0.f, 0.f);
            }
            *(float4*)(xs + row * XSS + col) = v;
        }
    }
    __syncthreads();

    const int nl = tid / TPN;            // node within block
    const int c0 = (tid % TPN) * CPT;    // first channel
    const int n = n0 + nl;
    if (n >= NN) return;

    float acc[CPT];
#pragma unroll
    for (int j = 0; j < CPT; j++) acc[j] = 0.f;

    const float* xr = xs + nl * XSS;
#pragma unroll
    for (int k = 0; k < KIN; k++) {
        const float xv = xr[k];
        const float4 w0 = *(const float4*)(Ws + k * COUT + c0);
        const float4 w1 = *(const float4*)(Ws + k * COUT + c0 + 4);
        acc[0] = fmaf(xv, w0.x, acc[0]);
        acc[1] = fmaf(xv, w0.y, acc[1]);
        acc[2] = fmaf(xv, w0.z, acc[2]);
        acc[3] = fmaf(xv, w0.w, acc[3]);
        acc[4] = fmaf(xv, w1.x, acc[4]);
        acc[5] = fmaf(xv, w1.y, acc[5]);
        acc[6] = fmaf(xv, w1.z, acc[6]);
        acc[7] = fmaf(xv, w1.w, acc[7]);
    }

    const float d = g_dinv[n];
    float4 s0, s1, o0, o1;
    s0.x = acc[0] * d; s0.y = acc[1] * d; s0.z = acc[2] * d; s0.w = acc[3] * d;
    s1.x = acc[4] * d; s1.y = acc[5] * d; s1.z = acc[6] * d; s1.w = acc[7] * d;
    o0.x = fmaf(s0.x, d, bs[c0 + 0]); o0.y = fmaf(s0.y, d, bs[c0 + 1]);
    o0.z = fmaf(s0.z, d, bs[c0 + 2]); o0.w = fmaf(s0.w, d, bs[c0 + 3]);
    o1.x = fmaf(s1.x, d, bs[c0 + 4]); o1.y = fmaf(s1.y, d, bs[c0 + 5]);
    o1.z = fmaf(s1.z, d, bs[c0 + 6]); o1.w = fmaf(s1.w, d, bs[c0 + 7]);

    float* xp = xws + (long)n * COUT + c0;
    float* op = out + (long)n * COUT + c0;
    *(float4*)(xp) = s0;     *(float4*)(xp + 4) = s1;
    *(float4*)(op) = o0;     *(float4*)(op + 4) = o1;
}

// ------------------------------------------------------------------
// Edge scatter: out[dst] += xws[src] * dinv[dst]   (vector red, 16B)
// COUT/4 threads per edge.
// ------------------------------------------------------------------
template <int COUT>
__global__ void k_scatter(const int* __restrict__ ei,
                          const float* __restrict__ xws,
                          float* __restrict__ out) {
    const int TPE = COUT / 4;
    const int gid = blockIdx.x * blockDim.x + threadIdx.x;
    const int e = gid / TPE;
    const int t = gid % TPE;
    if (e >= EE) return;
    const int src = __ldg(&ei[e]);
    const int dst = __ldg(&ei[EE + e]);
    const float dd = __ldg(&g_dinv[dst]);
    const float4 v = *(const float4*)(xws + (long)src * COUT + t * 4);
    float* p = out + (long)dst * COUT + t * 4;
    asm volatile("red.global.add.v4.f32 [%0], {%1, %2, %3, %4};"
                 :: "l"(p), "f"(v.x * dd), "f"(v.y * dd), "f"(v.z * dd), "f"(v.w * dd)
                 : "memory");
}

// ------------------------------------------------------------------
// Global mean pool (smem-privatized), input relu'd on read
// ------------------------------------------------------------------
__global__ void k_pool(const int* __restrict__ batch, const float* __restrict__ h) {
    __shared__ float ss[GG * HC];
    __shared__ float sc[GG];
    const int tid = threadIdx.x;
    for (int i = tid; i < GG * HC; i += 256) ss[i] = 0.f;
    if (tid < GG) sc[tid] = 0.f;
    __syncthreads();

    const int c = tid % HC;
    const int r = tid / HC;
    for (int n = blockIdx.x * 4 + r; n < NN; n += gridDim.x * 4) {
        const int g = __ldg(&batch[n]);
        const float v = fmaxf(h[(long)n * HC + c], 0.f);
        atomicAdd(&ss[g * HC + c], v);
        if (c == 0) atomicAdd(&sc[g], 1.f);
    }
    __syncthreads();
    for (int i = tid; i < GG * HC; i += 256)
        if (ss[i] != 0.f) atomicAdd(&g_sums[i], ss[i]);
    if (tid < GG && sc[tid] != 0.f) atomicAdd(&g_cnt[tid], sc[tid]);
}

__global__ void k_pooldiv() {
    int i = blockIdx.x * blockDim.x + threadIdx.x;
    if (i < GG * HC) {
        int g = i / HC;
        g_pool[i] = g_sums[i] / fmaxf(g_cnt[g], 1.0f);
    }
}

// z = pool @ W_proj + b_proj  -> g_z and d_out tail. one block of 1024.
__global__ void k_zproj(const float* __restrict__ Wp, const float* __restrict__ bp,
                        float* __restrict__ zout) {
    const int tid = threadIdx.x;           // 0..1023
    const int g = tid / LC, l = tid % LC;
    float s = bp[l];
#pragma unroll
    for (int k = 0; k < HC; k++) s = fmaf(g_pool[g * HC + k], Wp[k * LC + l], s);
    g_z[g * LC + l] = s;
    zout[g * LC + l] = s;
}

// d = relu(z[batch] @ W_dec_proj + b)  -> out (stored relu'd)
__global__ void k_decproj(const int* __restrict__ batch,
                          const float* __restrict__ Wdp,
                          const float* __restrict__ bdp,
                          float* __restrict__ out) {
    __shared__ float zs[GG * LC];
    __shared__ float Ws[LC * HC];
    __shared__ float bs[HC];
    const int tid = threadIdx.x;
    for (int i = tid; i < GG * LC; i += 256) zs[i] = g_z[i];
    for (int i = tid; i < LC * HC; i += 256) Ws[i] = Wdp[i];
    if (tid < HC) bs[tid] = bdp[tid];
    __syncthreads();

    const int c = tid % HC;
    const int r = tid / HC;
    const int n = blockIdx.x * 4 + r;
    if (n >= NN) return;
    const int g = __ldg(&batch[n]);
    float s = bs[c];
#pragma unroll
    for (int k = 0; k < LC; k++) s = fmaf(zs[g * LC + k], Ws[k * HC + c], s);
    out[(long)n * HC + c] = fmaxf(s, 0.f);
}

// ------------------------------------------------------------------
extern "C" void kernel_launch(void* const* d_in, const int* in_sizes, int n_in,
                              void* d_out, int out_size) {
    const float* x       = (const float*)d_in[0];
    const int*   ei      = (const int*)  d_in[1];
    const int*   batch   = (const int*)  d_in[2];
    const float* W_enc0  = (const float*)d_in[3];
    const float* b_enc0  = (const float*)d_in[4];
    const float* W_enc1  = (const float*)d_in[5];
    const float* b_enc1  = (const float*)d_in[6];
    const float* W_enc2  = (const float*)d_in[7];
    const float* b_enc2  = (const float*)d_in[8];
    const float* W_proj  = (const float*)d_in[9];
    const float* b_proj  = (const float*)d_in[10];
    const float* W_decp  = (const float*)d_in[11];
    const float* b_decp  = (const float*)d_in[12];
    const float* W_dec0  = (const float*)d_in[13];
    const float* b_dec0  = (const float*)d_in[14];
    const float* W_dec1  = (const float*)d_in[15];
    const float* b_dec1  = (const float*)d_in[16];

    float* out  = (float*)d_out;
    float* xrec = out;             // [NN, INC]
    float* zout = out + NN * INC;  // [GG, LC]

    float *p_xws, *p_buf0, *p_buf1;
    cudaGetSymbolAddress((void**)&p_xws,  g_xws);
    cudaGetSymbolAddress((void**)&p_buf0, g_buf0);
    cudaGetSymbolAddress((void**)&p_buf1, g_buf1);

    const int TB = 256;
    const int gN   = (NN + TB - 1) / TB;
    const int gE   = (EE + TB - 1) / TB;
    const int gA64 = (NN + 31) / 32;        // COUT=64: 32 nodes/block
    const int gA32 = (NN + 63) / 64;        // COUT=32: 64 nodes/block
    const int gD64 = (NN + 3) / 4;          // k_decproj: 4 nodes/block
    const int gS64 = (EE * 16 + TB - 1) / TB;
    const int gS32 = (EE * 8  + TB - 1) / TB;

    // degree + dinv (+ zero pool accumulators)
    k_zero<<<gN, TB>>>();
    k_count<<<gE, TB>>>(ei);
    k_dinv<<<gN, TB>>>();

    // encoder conv0: x[N,32] -> buf0
    k_gemm_self<INC, HC, false><<<gA64, TB>>>(x, W_enc0, b_enc0, p_xws, p_buf0);
    k_scatter<HC><<<gS64, TB>>>(ei, p_xws, p_buf0);
    // conv1: relu(buf0) -> buf1
    k_gemm_self<HC, HC, true><<<gA64, TB>>>(p_buf0, W_enc1, b_enc1, p_xws, p_buf1);
    k_scatter<HC><<<gS64, TB>>>(ei, p_xws, p_buf1);
    // conv2: relu(buf1) -> buf0
    k_gemm_self<HC, HC, true><<<gA64, TB>>>(p_buf1, W_enc2, b_enc2, p_xws, p_buf0);
    k_scatter<HC><<<gS64, TB>>>(ei, p_xws, p_buf0);

    // pool relu(buf0) -> g_pool ; z
    k_pool<<<592, TB>>>(batch, p_buf0);
    k_pooldiv<<<(GG * HC + TB - 1) / TB, TB>>>();
    k_zproj<<<1, 1024>>>(W_proj, b_proj, zout);

    // decoder broadcast projection -> buf1 (relu'd)
    k_decproj<<<gD64, TB>>>(batch, W_decp, b_decp, p_buf1);
    // dec conv0: buf1 (already relu'd) -> buf0
    k_gemm_self<HC, HC, false><<<gA64, TB>>>(p_buf1, W_dec0, b_dec0, p_xws, p_buf0);
    k_scatter<HC><<<gS64, TB>>>(ei, p_xws, p_buf0);
    // dec conv1: relu(buf0) -> x_recon [N,32]
    k_gemm_self<HC, INC, true><<<gA32, TB>>>(p_buf0, W_dec1, b_dec1, p_xws, xrec);
    k_scatter<INC><<<gS32, TB>>>(ei, p_xws, xrec);
}

// round 3
// speedup vs baseline: 1.5859x; 1.3402x over previous
#include <cuda_runtime.h>
#include <math.h>

#define NN 100000
#define EE 1600000
#define INC 32
#define HC  64
#define LC  16
#define GG  64

// ---- device scratch (static, no allocation) ----
__device__ float g_deg[NN];
__device__ float g_dinv[NN];
__device__ float g_xws[NN * HC];
__device__ float g_buf0[NN * HC];
__device__ float g_buf1[NN * HC];
__device__ float g_sums[GG * HC];
__device__ float g_cnt[GG];
__device__ float g_pool[GG * HC];
__device__ float g_z[GG * LC];

// ------------------------------------------------------------------
__global__ void k_zero() {
    int i = blockIdx.x * blockDim.x + threadIdx.x;
    if (i < NN) g_deg[i] = 0.f;
    if (i < GG * HC) g_sums[i] = 0.f;
    if (i < GG) g_cnt[i] = 0.f;
}

__global__ void k_count(const int* __restrict__ ei) {
    int e = blockIdx.x * blockDim.x + threadIdx.x;
    if (e < EE) atomicAdd(&g_deg[ei[EE + e]], 1.0f);
}

__global__ void k_dinv() {
    int i = blockIdx.x * blockDim.x + threadIdx.x;
    if (i < NN) g_dinv[i] = rsqrtf(g_deg[i] + 1.0f);
}

// ------------------------------------------------------------------
// GEMM + self-loop seed:  xws = (in@W)*dinv,  out = (in@W)*dinv^2 + b
// Register-blocked 4 nodes x 8 channels per thread. blockDim = 256.
// Per k: 2x LDS.128 (W) + 4 scalar LDS (x) feed 32 FMAs -> FMA-bound.
// ------------------------------------------------------------------
template <int KIN, int COUT, bool RELUIN>
__global__ void __launch_bounds__(256, 2)
k_gemm_self(const float* __restrict__ in,
            const float* __restrict__ W,
            const float* __restrict__ b,
            float* __restrict__ xws,
            float* __restrict__ out) {
    constexpr int TPN = COUT / 8;     // threads per node-group (8 or 4)
    constexpr int NG  = 256 / TPN;    // node-groups per block (32 or 64)
    constexpr int NPB = NG * 4;       // nodes per block (128 or 256)
    constexpr int XSS = KIN + 1;      // odd smem stride -> conflict-free

    __shared__ float Ws[KIN * COUT];
    __shared__ float bs[COUT];
    __shared__ float xs[NPB * XSS];

    const int tid = threadIdx.x;
    const int n0 = blockIdx.x * NPB;

    // stage W (float4 LDG -> float4 STS; counts divide 256 evenly)
    {
        const float4* W4 = (const float4*)W;
        float4* Ws4 = (float4*)Ws;
#pragma unroll
        for (int i = tid; i < KIN * COUT / 4; i += 256) Ws4[i] = W4[i];
    }
    if (tid < COUT) bs[tid] = b[tid];

    // stage input rows: float4 global load, 4 scalar STS (relu folded)
    {
        constexpr int QPR = KIN / 4;             // quads per row
        constexpr int NQ = NPB * QPR;
        for (int i = tid; i < NQ; i += 256) {
            const int row = i / QPR;
            const int qc = i % QPR;
            float4 v = make_float4(0.f, 0.f, 0.f, 0.f);
            if (n0 + row < NN) {
                v = *(const float4*)(in + (long)(n0 + row) * KIN + qc * 4);
                if (RELUIN) {
                    v.x = fmaxf(v.x, 0.f); v.y = fmaxf(v.y, 0.f);
                    v.z = fmaxf(v.z, 0.f); v.w = fmaxf(v.w, 0.f);
                }
            }
            float* p = xs + row * XSS + qc * 4;
            p[0] = v.x; p[1] = v.y; p[2] = v.z; p[3] = v.w;
        }
    }
    __syncthreads();

    const int tc = tid % TPN;            // channel group
    const int ng = tid / TPN;            // node group
    const int c0 = tc * 8;
    const int nb = ng * 4;               // local node base

    float acc[4][8];
#pragma unroll
    for (int j = 0; j < 4; j++)
#pragma unroll
        for (int m = 0; m < 8; m++) acc[j][m] = 0.f;

    const float4* Ws4 = (const float4*)Ws;
#pragma unroll 8
    for (int k = 0; k < KIN; k++) {
        const float4 w0 = Ws4[(k * COUT + c0) >> 2];
        const float4 w1 = Ws4[((k * COUT + c0) >> 2) + 1];
        float xv[4];
#pragma unroll
        for (int j = 0; j < 4; j++) xv[j] = xs[(nb + j) * XSS + k];
#pragma unroll
        for (int j = 0; j < 4; j++) {
            acc[j][0] = fmaf(xv[j], w0.x, acc[j][0]);
            acc[j][1] = fmaf(xv[j], w0.y, acc[j][1]);
            acc[j][2] = fmaf(xv[j], w0.z, acc[j][2]);
            acc[j][3] = fmaf(xv[j], w0.w, acc[j][3]);
            acc[j][4] = fmaf(xv[j], w1.x, acc[j][4]);
            acc[j][5] = fmaf(xv[j], w1.y, acc[j][5]);
            acc[j][6] = fmaf(xv[j], w1.z, acc[j][6]);
            acc[j][7] = fmaf(xv[j], w1.w, acc[j][7]);
        }
    }

#pragma unroll
    for (int j = 0; j < 4; j++) {
        const int n = n0 + nb + j;
        if (n >= NN) break;
        const float d = g_dinv[n];
        float4 s0, s1, o0, o1;
        s0.x = acc[j][0] * d; s0.y = acc[j][1] * d;
        s0.z = acc[j][2] * d; s0.w = acc[j][3] * d;
        s1.x = acc[j][4] * d; s1.y = acc[j][5] * d;
        s1.z = acc[j][6] * d; s1.w = acc[j][7] * d;
        o0.x = fmaf(s0.x, d, bs[c0 + 0]); o0.y = fmaf(s0.y, d, bs[c0 + 1]);
        o0.z = fmaf(s0.z, d, bs[c0 + 2]); o0.w = fmaf(s0.w, d, bs[c0 + 3]);
        o1.x = fmaf(s1.x, d, bs[c0 + 4]); o1.y = fmaf(s1.y, d, bs[c0 + 5]);
        o1.z = fmaf(s1.z, d, bs[c0 + 6]); o1.w = fmaf(s1.w, d, bs[c0 + 7]);
        float* xp = xws + (long)n * COUT + c0;
        float* op = out + (long)n * COUT + c0;
        *(float4*)(xp) = s0; *(float4*)(xp + 4) = s1;
        *(float4*)(op) = o0; *(float4*)(op + 4) = o1;
    }
}

// ------------------------------------------------------------------
// Edge scatter: out[dst] += xws[src] * dinv[dst]   (vector red, 16B)
// ------------------------------------------------------------------
template <int COUT>
__global__ void k_scatter(const int* __restrict__ ei,
                          const float* __restrict__ xws,
                          float* __restrict__ out) {
    const int TPE = COUT / 4;
    const int gid = blockIdx.x * blockDim.x + threadIdx.x;
    const int e = gid / TPE;
    const int t = gid % TPE;
    if (e >= EE) return;
    const int src = __ldg(&ei[e]);
    const int dst = __ldg(&ei[EE + e]);
    const float dd = __ldg(&g_dinv[dst]);
    const float4 v = *(const float4*)(xws + (long)src * COUT + t * 4);
    float* p = out + (long)dst * COUT + t * 4;
    asm volatile("red.global.add.v4.f32 [%0], {%1, %2, %3, %4};"
                 :: "l"(p), "f"(v.x * dd), "f"(v.y * dd), "f"(v.z * dd), "f"(v.w * dd)
                 : "memory");
}

// ------------------------------------------------------------------
__global__ void k_pool(const int* __restrict__ batch, const float* __restrict__ h) {
    __shared__ float ss[GG * HC];
    __shared__ float sc[GG];
    const int tid = threadIdx.x;
    for (int i = tid; i < GG * HC; i += 256) ss[i] = 0.f;
    if (tid < GG) sc[tid] = 0.f;
    __syncthreads();

    const int c = tid % HC;
    const int r = tid / HC;
    for (int n = blockIdx.x * 4 + r; n < NN; n += gridDim.x * 4) {
        const int g = __ldg(&batch[n]);
        const float v = fmaxf(h[(long)n * HC + c], 0.f);
        atomicAdd(&ss[g * HC + c], v);
        if (c == 0) atomicAdd(&sc[g], 1.f);
    }
    __syncthreads();
    for (int i = tid; i < GG * HC; i += 256)
        if (ss[i] != 0.f) atomicAdd(&g_sums[i], ss[i]);
    if (tid < GG && sc[tid] != 0.f) atomicAdd(&g_cnt[tid], sc[tid]);
}

__global__ void k_pooldiv() {
    int i = blockIdx.x * blockDim.x + threadIdx.x;
    if (i < GG * HC) {
        int g = i / HC;
        g_pool[i] = g_sums[i] / fmaxf(g_cnt[g], 1.0f);
    }
}

__global__ void k_zproj(const float* __restrict__ Wp, const float* __restrict__ bp,
                        float* __restrict__ zout) {
    const int tid = threadIdx.x;           // 0..1023
    const int g = tid / LC, l = tid % LC;
    float s = bp[l];
#pragma unroll
    for (int k = 0; k < HC; k++) s = fmaf(g_pool[g * HC + k], Wp[k * LC + l], s);
    g_z[g * LC + l] = s;
    zout[g * LC + l] = s;
}

__global__ void k_decproj(const int* __restrict__ batch,
                          const float* __restrict__ Wdp,
                          const float* __restrict__ bdp,
                          float* __restrict__ out) {
    __shared__ float zs[GG * LC];
    __shared__ float Ws[LC * HC];
    __shared__ float bs[HC];
    const int tid = threadIdx.x;
    for (int i = tid; i < GG * LC; i += 256) zs[i] = g_z[i];
    for (int i = tid; i < LC * HC; i += 256) Ws[i] = Wdp[i];
    if (tid < HC) bs[tid] = bdp[tid];
    __syncthreads();

    const int c = tid % HC;
    const int r = tid / HC;
    const int n = blockIdx.x * 4 + r;
    if (n >= NN) return;
    const int g = __ldg(&batch[n]);
    float s = bs[c];
#pragma unroll
    for (int k = 0; k < LC; k++) s = fmaf(zs[g * LC + k], Ws[k * HC + c], s);
    out[(long)n * HC + c] = fmaxf(s, 0.f);
}

// ------------------------------------------------------------------
extern "C" void kernel_launch(void* const* d_in, const int* in_sizes, int n_in,
                              void* d_out, int out_size) {
    const float* x       = (const float*)d_in[0];
    const int*   ei      = (const int*)  d_in[1];
    const int*   batch   = (const int*)  d_in[2];
    const float* W_enc0  = (const float*)d_in[3];
    const float* b_enc0  = (const float*)d_in[4];
    const float* W_enc1  = (const float*)d_in[5];
    const float* b_enc1  = (const float*)d_in[6];
    const float* W_enc2  = (const float*)d_in[7];
    const float* b_enc2  = (const float*)d_in[8];
    const float* W_proj  = (const float*)d_in[9];
    const float* b_proj  = (const float*)d_in[10];
    const float* W_decp  = (const float*)d_in[11];
    const float* b_decp  = (const float*)d_in[12];
    const float* W_dec0  = (const float*)d_in[13];
    const float* b_dec0  = (const float*)d_in[14];
    const float* W_dec1  = (const float*)d_in[15];
    const float* b_dec1  = (const float*)d_in[16];

    float* out  = (float*)d_out;
    float* xrec = out;             // [NN, INC]
    float* zout = out + NN * INC;  // [GG, LC]

    float *p_xws, *p_buf0, *p_buf1;
    cudaGetSymbolAddress((void**)&p_xws,  g_xws);
    cudaGetSymbolAddress((void**)&p_buf0, g_buf0);
    cudaGetSymbolAddress((void**)&p_buf1, g_buf1);

    const int TB = 256;
    const int gN   = (NN + TB - 1) / TB;
    const int gE   = (EE + TB - 1) / TB;
    const int gA64 = (NN + 127) / 128;      // COUT=64: 128 nodes/block
    const int gA32 = (NN + 255) / 256;      // COUT=32: 256 nodes/block
    const int gD64 = (NN + 3) / 4;          // k_decproj: 4 nodes/block
    const int gS64 = (EE * 16 + TB - 1) / TB;
    const int gS32 = (EE * 8  + TB - 1) / TB;

    k_zero<<<gN, TB>>>();
    k_count<<<gE, TB>>>(ei);
    k_dinv<<<gN, TB>>>();

    // encoder conv0: x[N,32] -> buf0
    k_gemm_self<INC, HC, false><<<gA64, TB>>>(x, W_enc0, b_enc0, p_xws, p_buf0);
    k_scatter<HC><<<gS64, TB>>>(ei, p_xws, p_buf0);
    // conv1: relu(buf0) -> buf1
    k_gemm_self<HC, HC, true><<<gA64, TB>>>(p_buf0, W_enc1, b_enc1, p_xws, p_buf1);
    k_scatter<HC><<<gS64, TB>>>(ei, p_xws, p_buf1);
    // conv2: relu(buf1) -> buf0
    k_gemm_self<HC, HC, true><<<gA64, TB>>>(p_buf1, W_enc2, b_enc2, p_xws, p_buf0);
    k_scatter<HC><<<gS64, TB>>>(ei, p_xws, p_buf0);

    // pool relu(buf0) -> g_pool ; z
    k_pool<<<592, TB>>>(batch, p_buf0);
    k_pooldiv<<<(GG * HC + TB - 1) / TB, TB>>>();
    k_zproj<<<1, 1024>>>(W_proj, b_proj, zout);

    // decoder broadcast projection -> buf1 (relu'd)
    k_decproj<<<gD64, TB>>>(batch, W_decp, b_decp, p_buf1);
    // dec conv0: buf1 (already relu'd) -> buf0
    k_gemm_self<HC, HC, false><<<gA64, TB>>>(p_buf1, W_dec0, b_dec0, p_xws, p_buf0);
    k_scatter<HC><<<gS64, TB>>>(ei, p_xws, p_buf0);
    // dec conv1: relu(buf0) -> x_recon [N,32]
    k_gemm_self<HC, INC, true><<<gA32, TB>>>(p_buf0, W_dec1, b_dec1, p_xws, xrec);
    k_scatter<INC><<<gS32, TB>>>(ei, p_xws, xrec);
}

// round 5
// speedup vs baseline: 1.6186x; 1.0207x over previous
#include <cuda_runtime.h>
#include <math.h>

#define NN 100000
#define EE 1600000
#define INC 32
#define HC  64
#define LC  16
#define GG  64

// ---- device scratch (static, no allocation) ----
__device__ float g_deg[NN];
__device__ float g_dinv[NN];
__device__ float g_xws[NN * HC];
__device__ float g_buf0[NN * HC];
__device__ float g_buf1[NN * HC];
__device__ float g_sums[GG * HC];
__device__ float g_cnt[GG];
__device__ float g_pool[GG * HC];
__device__ float g_z[GG * LC];
__device__ float g_XW[GG * HC];     // (relu(z@Wdp+b)) @ W_dec0, per graph

// ------------------------------------------------------------------
__global__ void k_zero() {
    int i = blockIdx.x * blockDim.x + threadIdx.x;
    if (i < NN) g_deg[i] = 0.f;
    if (i < GG * HC) g_sums[i] = 0.f;
    if (i < GG) g_cnt[i] = 0.f;
}

__global__ void k_count(const int* __restrict__ ei) {
    int e = blockIdx.x * blockDim.x + threadIdx.x;
    if (e < EE) atomicAdd(&g_deg[ei[EE + e]], 1.0f);
}

__global__ void k_dinv() {
    int i = blockIdx.x * blockDim.x + threadIdx.x;
    if (i < NN) g_dinv[i] = rsqrtf(g_deg[i] + 1.0f);
}

// ------------------------------------------------------------------
// conv0 pre-aggregation seed: agg[n] = x[n] * dinv[n]^2   (32 ch)
// ------------------------------------------------------------------
__global__ void k_seedx(const float* __restrict__ x, float* __restrict__ agg) {
    const int gid = blockIdx.x * blockDim.x + threadIdx.x;
    const int n = gid / 8;
    const int t = gid % 8;
    if (n >= NN) return;
    const float d = __ldg(&g_dinv[n]);
    const float dd = d * d;
    float4 v = *(const float4*)(x + (long)n * INC + t * 4);
    v.x *= dd; v.y *= dd; v.z *= dd; v.w *= dd;
    *(float4*)(agg + (long)n * INC + t * 4) = v;
}

// conv0 scatter on raw x: agg[dst] += x[src] * dinv[src] * dinv[dst]
__global__ void k_scatter_x(const int* __restrict__ ei,
                            const float* __restrict__ x,
                            float* __restrict__ agg) {
    const int gid = blockIdx.x * blockDim.x + threadIdx.x;
    const int e = gid / 8;
    const int t = gid % 8;
    if (e >= EE) return;
    const int src = __ldg(&ei[e]);
    const int dst = __ldg(&ei[EE + e]);
    const float c = __ldg(&g_dinv[src]) * __ldg(&g_dinv[dst]);
    const float4 v = *(const float4*)(x + (long)src * INC + t * 4);
    float* p = agg + (long)dst * INC + t * 4;
    asm volatile("red.global.add.v4.f32 [%0], {%1, %2, %3, %4};"
                 :: "l"(p), "f"(v.x * c), "f"(v.y * c), "f"(v.z * c), "f"(v.w * c)
                 : "memory");
}

// ------------------------------------------------------------------
// GEMM: register-blocked 4 nodes x 8 channels per thread. blockDim=256.
// SELF=true : xws = (in@W)*dinv, out = (in@W)*dinv^2 + b
// SELF=false: out = in@W + b    (xws unused)
// ------------------------------------------------------------------
template <int KIN, int COUT, bool RELUIN, bool SELF>
__global__ void __launch_bounds__(256, 3)
k_gemm_self(const float* __restrict__ in,
            const float* __restrict__ W,
            const float* __restrict__ b,
            float* __restrict__ xws,
            float* __restrict__ out) {
    constexpr int TPN = COUT / 8;
    constexpr int NG  = 256 / TPN;
    constexpr int NPB = NG * 4;
    constexpr int XSS = KIN + 1;

    __shared__ float Ws[KIN * COUT];
    __shared__ float bs[COUT];
    __shared__ float xs[NPB * XSS];

    const int tid = threadIdx.x;
    const int n0 = blockIdx.x * NPB;

    {
        const float4* W4 = (const float4*)W;
        float4* Ws4 = (float4*)Ws;
#pragma unroll
        for (int i = tid; i < KIN * COUT / 4; i += 256) Ws4[i] = W4[i];
    }
    if (tid < COUT) bs[tid] = b[tid];

    {
        constexpr int QPR = KIN / 4;
        constexpr int NQ = NPB * QPR;
        for (int i = tid; i < NQ; i += 256) {
            const int row = i / QPR;
            const int qc = i % QPR;
            float4 v = make_float4(0.f, 0.f, 0.f, 0.f);
            if (n0 + row < NN) {
                v = *(const float4*)(in + (long)(n0 + row) * KIN + qc * 4);
                if (RELUIN) {
                    v.x = fmaxf(v.x, 0.f); v.y = fmaxf(v.y, 0.f);
                    v.z = fmaxf(v.z, 0.f); v.w = fmaxf(v.w, 0.f);
                }
            }
            float* p = xs + row * XSS + qc * 4;
            p[0] = v.x; p[1] = v.y; p[2] = v.z; p[3] = v.w;
        }
    }
    __syncthreads();

    const int tc = tid % TPN;
    const int ng = tid / TPN;
    const int c0 = tc * 8;
    const int nb = ng * 4;

    float acc[4][8];
#pragma unroll
    for (int j = 0; j < 4; j++)
#pragma unroll
        for (int m = 0; m < 8; m++) acc[j][m] = 0.f;

    const float4* Ws4 = (const float4*)Ws;
#pragma unroll 8
    for (int k = 0; k < KIN; k++) {
        const float4 w0 = Ws4[(k * COUT + c0) >> 2];
        const float4 w1 = Ws4[((k * COUT + c0) >> 2) + 1];
        float xv[4];
#pragma unroll
        for (int j = 0; j < 4; j++) xv[j] = xs[(nb + j) * XSS + k];
#pragma unroll
        for (int j = 0; j < 4; j++) {
            acc[j][0] = fmaf(xv[j], w0.x, acc[j][0]);
            acc[j][1] = fmaf(xv[j], w0.y, acc[j][1]);
            acc[j][2] = fmaf(xv[j], w0.z, acc[j][2]);
            acc[j][3] = fmaf(xv[j], w0.w, acc[j][3]);
            acc[j][4] = fmaf(xv[j], w1.x, acc[j][4]);
            acc[j][5] = fmaf(xv[j], w1.y, acc[j][5]);
            acc[j][6] = fmaf(xv[j], w1.z, acc[j][6]);
            acc[j][7] = fmaf(xv[j], w1.w, acc[j][7]);
        }
    }

#pragma unroll
    for (int j = 0; j < 4; j++) {
        const int n = n0 + nb + j;
        if (n >= NN) break;
        if (SELF) {
            const float d = g_dinv[n];
            float4 s0, s1, o0, o1;
            s0.x = acc[j][0] * d; s0.y = acc[j][1] * d;
            s0.z = acc[j][2] * d; s0.w = acc[j][3] * d;
            s1.x = acc[j][4] * d; s1.y = acc[j][5] * d;
            s1.z = acc[j][6] * d; s1.w = acc[j][7] * d;
            o0.x = fmaf(s0.x, d, bs[c0 + 0]); o0.y = fmaf(s0.y, d, bs[c0 + 1]);
            o0.z = fmaf(s0.z, d, bs[c0 + 2]); o0.w = fmaf(s0.w, d, bs[c0 + 3]);
            o1.x = fmaf(s1.x, d, bs[c0 + 4]); o1.y = fmaf(s1.y, d, bs[c0 + 5]);
            o1.z = fmaf(s1.z, d, bs[c0 + 6]); o1.w = fmaf(s1.w, d, bs[c0 + 7]);
            float* xp = xws + (long)n * COUT + c0;
            float* op = out + (long)n * COUT + c0;
            *(float4*)(xp) = s0; *(float4*)(xp + 4) = s1;
            *(float4*)(op) = o0; *(float4*)(op + 4) = o1;
        } else {
            float4 o0, o1;
            o0.x = acc[j][0] + bs[c0 + 0]; o0.y = acc[j][1] + bs[c0 + 1];
            o0.z = acc[j][2] + bs[c0 + 2]; o0.w = acc[j][3] + bs[c0 + 3];
            o1.x = acc[j][4] + bs[c0 + 4]; o1.y = acc[j][5] + bs[c0 + 5];
            o1.z = acc[j][6] + bs[c0 + 6]; o1.w = acc[j][7] + bs[c0 + 7];
            float* op = out + (long)n * COUT + c0;
            *(float4*)(op) = o0; *(float4*)(op + 4) = o1;
        }
    }
}

// ------------------------------------------------------------------
// Edge scatter: out[dst] += xws[src] * dinv[dst]   (vector red, 16B)
// ------------------------------------------------------------------
template <int COUT>
__global__ void k_scatter(const int* __restrict__ ei,
                          const float* __restrict__ xws,
                          float* __restrict__ out) {
    const int TPE = COUT / 4;
    const int gid = blockIdx.x * blockDim.x + threadIdx.x;
    const int e = gid / TPE;
    const int t = gid % TPE;
    if (e >= EE) return;
    const int src = __ldg(&ei[e]);
    const int dst = __ldg(&ei[EE + e]);
    const float dd = __ldg(&g_dinv[dst]);
    const float4 v = *(const float4*)(xws + (long)src * COUT + t * 4);
    float* p = out + (long)dst * COUT + t * 4;
    asm volatile("red.global.add.v4.f32 [%0], {%1, %2, %3, %4};"
                 :: "l"(p), "f"(v.x * dd), "f"(v.y * dd), "f"(v.z * dd), "f"(v.w * dd)
                 : "memory");
}

// ------------------------------------------------------------------
__global__ void k_pool(const int* __restrict__ batch, const float* __restrict__ h) {
    __shared__ float ss[GG * HC];
    __shared__ float sc[GG];
    const int tid = threadIdx.x;
    for (int i = tid; i < GG * HC; i += 256) ss[i] = 0.f;
    if (tid < GG) sc[tid] = 0.f;
    __syncthreads();

    const int c = tid % HC;
    const int r = tid / HC;
    for (int n = blockIdx.x * 4 + r; n < NN; n += gridDim.x * 4) {
        const int g = __ldg(&batch[n]);
        const float v = fmaxf(h[(long)n * HC + c], 0.f);
        atomicAdd(&ss[g * HC + c], v);
        if (c == 0) atomicAdd(&sc[g], 1.f);
    }
    __syncthreads();
    for (int i = tid; i < GG * HC; i += 256)
        if (ss[i] != 0.f) atomicAdd(&g_sums[i], ss[i]);
    if (tid < GG && sc[tid] != 0.f) atomicAdd(&g_cnt[tid], sc[tid]);
}

__global__ void k_pooldiv() {
    int i = blockIdx.x * blockDim.x + threadIdx.x;
    if (i < GG * HC) {
        int g = i / HC;
        g_pool[i] = g_sums[i] / fmaxf(g_cnt[g], 1.0f);
    }
}

__global__ void __launch_bounds__(1024)
k_zproj(const float* __restrict__ Wp, const float* __restrict__ bp,
        float* __restrict__ zout) {
    const int tid = threadIdx.x;           // 0..1023
    const int g = tid / LC, l = tid % LC;
    float s = bp[l];
#pragma unroll
    for (int k = 0; k < HC; k++) s = fmaf(g_pool[g * HC + k], Wp[k * LC + l], s);
    g_z[g * LC + l] = s;
    zout[g * LC + l] = s;
}

// ------------------------------------------------------------------
// Graph-space decoder head: D = relu(z@Wdp + bdp) [G,HC];
// XW = D @ W_dec0 [G,HC]. One block of 1024, reg-capped.
// ------------------------------------------------------------------
__global__ void __launch_bounds__(1024)
k_graphdec(const float* __restrict__ Wdp,
           const float* __restrict__ bdp,
           const float* __restrict__ Wd0) {
    __shared__ float zs[GG * LC];       // 4KB
    __shared__ float Ds[GG * HC];       // 16KB
    __shared__ float Wd0s[HC * HC];     // 16KB
    const int tid = threadIdx.x;        // 0..1023

    for (int i = tid; i < GG * LC; i += 1024) zs[i] = g_z[i];
    for (int i = tid; i < HC * HC; i += 1024) Wd0s[i] = Wd0[i];
    __syncthreads();

    for (int i = tid; i < GG * HC; i += 1024) {
        const int g = i / HC, c = i % HC;
        float s = bdp[c];
#pragma unroll
        for (int k = 0; k < LC; k++) s = fmaf(zs[g * LC + k], Wdp[k * HC + c], s);
        Ds[i] = fmaxf(s, 0.f);
    }
    __syncthreads();

    for (int i = tid; i < GG * HC; i += 1024) {
        const int g = i / HC, c = i % HC;
        float s = 0.f;
#pragma unroll 16
        for (int k = 0; k < HC; k++) s = fmaf(Ds[g * HC + k], Wd0s[k * HC + c], s);
        g_XW[i] = s;
    }
}

// seed dec0 out: out[n] = XW[batch[n]] * dinv[n]^2 + b_dec0
__global__ void k_seed_dec0(const int* __restrict__ batch,
                            const float* __restrict__ bd0,
                            float* __restrict__ out) {
    const int gid = blockIdx.x * blockDim.x + threadIdx.x;
    const int n = gid / 16;
    const int t = gid % 16;
    if (n >= NN) return;
    const int g = __ldg(&batch[n]);
    const float d = __ldg(&g_dinv[n]);
    const float dd = d * d;
    float4 v = *(const float4*)(g_XW + g * HC + t * 4);
    const float4 b4 = *(const float4*)(bd0 + t * 4);
    v.x = fmaf(v.x, dd, b4.x); v.y = fmaf(v.y, dd, b4.y);
    v.z = fmaf(v.z, dd, b4.z); v.w = fmaf(v.w, dd, b4.w);
    *(float4*)(out + (long)n * HC + t * 4) = v;
}

// dec0 scatter via graph table: out[dst] += dinv[src]*dinv[dst]*XW[batch[src]]
__global__ void k_scatter_tab(const int* __restrict__ ei,
                              const int* __restrict__ batch,
                              float* __restrict__ out) {
    __shared__ float XWs[GG * HC];      // 16KB
    const int tid = threadIdx.x;
    {
        const float4* s4 = (const float4*)g_XW;
        float4* d4 = (float4*)XWs;
        for (int i = tid; i < GG * HC / 4; i += 256) d4[i] = s4[i];
    }
    __syncthreads();

    const int gid = blockIdx.x * blockDim.x + tid;
    const int e = gid / 16;
    const int t = gid % 16;
    if (e >= EE) return;
    const int src = __ldg(&ei[e]);
    const int dst = __ldg(&ei[EE + e]);
    const int g = __ldg(&batch[src]);
    const float c = __ldg(&g_dinv[src]) * __ldg(&g_dinv[dst]);
    const float4 v = *(const float4*)(XWs + g * HC + t * 4);
    float* p = out + (long)dst * HC + t * 4;
    asm volatile("red.global.add.v4.f32 [%0], {%1, %2, %3, %4};"
                 :: "l"(p), "f"(v.x * c), "f"(v.y * c), "f"(v.z * c), "f"(v.w * c)
                 : "memory");
}

// ------------------------------------------------------------------
extern "C" void kernel_launch(void* const* d_in, const int* in_sizes, int n_in,
                              void* d_out, int out_size) {
    const float* x       = (const float*)d_in[0];
    const int*   ei      = (const int*)  d_in[1];
    const int*   batch   = (const int*)  d_in[2];
    const float* W_enc0  = (const float*)d_in[3];
    const float* b_enc0  = (const float*)d_in[4];
    const float* W_enc1  = (const float*)d_in[5];
    const float* b_enc1  = (const float*)d_in[6];
    const float* W_enc2  = (const float*)d_in[7];
    const float* b_enc2  = (const float*)d_in[8];
    const float* W_proj  = (const float*)d_in[9];
    const float* b_proj  = (const float*)d_in[10];
    const float* W_decp  = (const float*)d_in[11];
    const float* b_decp  = (const float*)d_in[12];
    const float* W_dec0  = (const float*)d_in[13];
    const float* b_dec0  = (const float*)d_in[14];
    const float* W_dec1  = (const float*)d_in[15];
    const float* b_dec1  = (const float*)d_in[16];

    float* out  = (float*)d_out;
    float* xrec = out;             // [NN, INC]
    float* zout = out + NN * INC;  // [GG, LC]

    float *p_xws, *p_buf0, *p_buf1;
    cudaGetSymbolAddress((void**)&p_xws,  g_xws);
    cudaGetSymbolAddress((void**)&p_buf0, g_buf0);
    cudaGetSymbolAddress((void**)&p_buf1, g_buf1);

    const int TB = 256;
    const int gN    = (NN + TB - 1) / TB;
    const int gE    = (EE + TB - 1) / TB;
    const int gA64  = (NN + 127) / 128;
    const int gA32  = (NN + 255) / 256;
    const int gN8   = (NN * 8  + TB - 1) / TB;
    const int gN16  = (NN * 16 + TB - 1) / TB;
    const int gS64  = (EE * 16 + TB - 1) / TB;
    const int gS32  = (EE * 8  + TB - 1) / TB;

    k_zero<<<gN, TB>>>();
    k_count<<<gE, TB>>>(ei);
    k_dinv<<<gN, TB>>>();

    // conv0: aggregate x in input space (32ch), then GEMM
    k_seedx<<<gN8, TB>>>(x, p_buf1);
    k_scatter_x<<<gS32, TB>>>(ei, x, p_buf1);
    k_gemm_self<INC, HC, false, false><<<gA64, TB>>>(p_buf1, W_enc0, b_enc0, p_xws, p_buf0);

    // conv1: relu(buf0) -> buf1
    k_gemm_self<HC, HC, true, true><<<gA64, TB>>>(p_buf0, W_enc1, b_enc1, p_xws, p_buf1);
    k_scatter<HC><<<gS64, TB>>>(ei, p_xws, p_buf1);
    // conv2: relu(buf1) -> buf0
    k_gemm_self<HC, HC, true, true><<<gA64, TB>>>(p_buf1, W_enc2, b_enc2, p_xws, p_buf0);
    k_scatter<HC><<<gS64, TB>>>(ei, p_xws, p_buf0);

    // pool relu(buf0) -> g_pool ; z
    k_pool<<<592, TB>>>(batch, p_buf0);
    k_pooldiv<<<(GG * HC + TB - 1) / TB, TB>>>();
    k_zproj<<<1, 1024>>>(W_proj, b_proj, zout);

    // decoder graph-space head: D = relu(z@Wdp+b); XW = D@W_dec0
    k_graphdec<<<1, 1024>>>(W_decp, b_decp, W_dec0);

    // dec conv0 via graph table -> buf1
    k_seed_dec0<<<gN16, TB>>>(batch, b_dec0, p_buf1);
    k_scatter_tab<<<gS64, TB>>>(ei, batch, p_buf1);

    // dec conv1: relu(buf1) -> x_recon [N,32]
    k_gemm_self<HC, INC, true, true><<<gA32, TB>>>(p_buf1, W_dec1, b_dec1, p_xws, xrec);
    k_scatter<INC><<<gS32, TB>>>(ei, p_xws, xrec);
}

// round 6
// speedup vs baseline: 2.2584x; 1.3952x over previous
#include <cuda_runtime.h>
#include <math.h>

#define NN 100000
#define EE 1600000
#define INC 32
#define HC  64
#define LC  16
#define GG  64
#define NB1 98          // ceil(NN/1024) scan blocks

// ---- device scratch (static, no allocation) ----
__device__ int   g_degi[NN];
__device__ int   g_part[NN];
__device__ int   g_off[NN];
__device__ int   g_cur[NN];
__device__ int   g_csr[EE];
__device__ int   g_bsum[128];
__device__ int   g_bbase[128];
__device__ float g_dinv[NN];
__device__ float g_xws[NN * HC];    // P = xw * dinv (per-conv payload)
__device__ float g_buf0[NN * HC];
__device__ float g_buf1[NN * HC];
__device__ float g_sums[GG * HC];
__device__ float g_cnt[GG];
__device__ float g_z[GG * LC];
__device__ float g_XW[GG * HC];     // (relu(z@Wdp+b)) @ W_dec0, per graph

// ------------------------------------------------------------------
__global__ void k_init() {
    int i = blockIdx.x * blockDim.x + threadIdx.x;
    if (i < NN) g_degi[i] = 0;
    if (i < GG * HC) g_sums[i] = 0.f;
    if (i < GG) g_cnt[i] = 0.f;
}

__global__ void k_count(const int* __restrict__ ei) {
    int e = blockIdx.x * blockDim.x + threadIdx.x;
    if (e < EE) atomicAdd(&g_degi[ei[EE + e]], 1);
}

// block-level exclusive scan of degi (1024/block)
__global__ void __launch_bounds__(1024) k_scan1() {
    __shared__ int sm[1024];
    const int tid = threadIdx.x;
    const int i = blockIdx.x * 1024 + tid;
    const int v = (i < NN) ? g_degi[i] : 0;
    sm[tid] = v;
    __syncthreads();
    for (int o = 1; o < 1024; o <<= 1) {
        int t = (tid >= o) ? sm[tid - o] : 0;
        __syncthreads();
        sm[tid] += t;
        __syncthreads();
    }
    if (i < NN) g_part[i] = sm[tid] - v;          // exclusive
    if (tid == 1023) g_bsum[blockIdx.x] = sm[1023];
}

__global__ void __launch_bounds__(128) k_scan2() {
    __shared__ int sm[128];
    const int tid = threadIdx.x;
    const int v = (tid < NB1) ? g_bsum[tid] : 0;
    sm[tid] = v;
    __syncthreads();
    for (int o = 1; o < 128; o <<= 1) {
        int t = (tid >= o) ? sm[tid - o] : 0;
        __syncthreads();
        sm[tid] += t;
        __syncthreads();
    }
    g_bbase[tid] = sm[tid] - v;                   // exclusive
}

__global__ void __launch_bounds__(1024) k_scan3() {
    const int i = blockIdx.x * 1024 + threadIdx.x;
    if (i >= NN) return;
    const int o = g_part[i] + g_bbase[blockIdx.x];
    g_off[i] = o;
    g_cur[i] = o;
    g_dinv[i] = rsqrtf((float)g_degi[i] + 1.0f);
}

__global__ void k_fill(const int* __restrict__ ei) {
    int e = blockIdx.x * blockDim.x + threadIdx.x;
    if (e >= EE) return;
    const int src = __ldg(&ei[e]);
    const int dst = __ldg(&ei[EE + e]);
    const int pos = atomicAdd(&g_cur[dst], 1);
    g_csr[pos] = src;
}

// ------------------------------------------------------------------
// P0[n] = x[n] * dinv[n]   (32 ch)
// ------------------------------------------------------------------
__global__ void k_P0(const float* __restrict__ x, float* __restrict__ P) {
    const int gid = blockIdx.x * blockDim.x + threadIdx.x;
    const int n = gid / 8;
    const int t = gid % 8;
    if (n >= NN) return;
    const float d = __ldg(&g_dinv[n]);
    float4 v = *(const float4*)(x + (long)n * INC + t * 4);
    v.x *= d; v.y *= d; v.z *= d; v.w *= d;
    *(float4*)(P + (long)n * INC + t * 4) = v;
}

// ------------------------------------------------------------------
// Gather aggregation (no atomics): out[n] = dinv[n]*(sum P[src] + P[n]) [+ b]
// ------------------------------------------------------------------
template <bool BIAS>
__global__ void __launch_bounds__(256)
k_gather64(const float* __restrict__ P, const float* __restrict__ b,
           float* __restrict__ out) {
    const int wid = threadIdx.x >> 5;
    const int lane = threadIdx.x & 31;
    const int n = blockIdx.x * 8 + wid;
    if (n >= NN) return;
    const int o = __ldg(&g_off[n]);
    const int d = __ldg(&g_degi[n]);

    float2 acc = *(const float2*)(P + (long)n * HC + lane * 2);  // self
    int i = 0;
    for (; i + 2 <= d; i += 2) {
        const int s0 = __ldg(&g_csr[o + i]);
        const int s1 = __ldg(&g_csr[o + i + 1]);
        const float2 v0 = *(const float2*)(P + (long)s0 * HC + lane * 2);
        const float2 v1 = *(const float2*)(P + (long)s1 * HC + lane * 2);
        acc.x += v0.x + v1.x;
        acc.y += v0.y + v1.y;
    }
    if (i < d) {
        const int s = __ldg(&g_csr[o + i]);
        const float2 v = *(const float2*)(P + (long)s * HC + lane * 2);
        acc.x += v.x; acc.y += v.y;
    }
    const float dn = __ldg(&g_dinv[n]);
    float2 r;
    if (BIAS) {
        r.x = fmaf(acc.x, dn, __ldg(&b[lane * 2]));
        r.y = fmaf(acc.y, dn, __ldg(&b[lane * 2 + 1]));
    } else {
        r.x = acc.x * dn; r.y = acc.y * dn;
    }
    *(float2*)(out + (long)n * HC + lane * 2) = r;
}

template <bool BIAS>
__global__ void __launch_bounds__(256)
k_gather32(const float* __restrict__ P, const float* __restrict__ b,
           float* __restrict__ out) {
    const int wid = threadIdx.x >> 5;
    const int lane = threadIdx.x & 31;
    const int n = blockIdx.x * 8 + wid;
    if (n >= NN) return;
    const int o = __ldg(&g_off[n]);
    const int d = __ldg(&g_degi[n]);

    float acc = P[(long)n * INC + lane];          // self
    int i = 0;
    for (; i + 4 <= d; i += 4) {
        const int s0 = __ldg(&g_csr[o + i]);
        const int s1 = __ldg(&g_csr[o + i + 1]);
        const int s2 = __ldg(&g_csr[o + i + 2]);
        const int s3 = __ldg(&g_csr[o + i + 3]);
        acc += P[(long)s0 * INC + lane] + P[(long)s1 * INC + lane]
             + P[(long)s2 * INC + lane] + P[(long)s3 * INC + lane];
    }
    for (; i < d; i++) {
        const int s = __ldg(&g_csr[o + i]);
        acc += P[(long)s * INC + lane];
    }
    const float dn = __ldg(&g_dinv[n]);
    float r = BIAS ? fmaf(acc, dn, __ldg(&b[lane])) : acc * dn;
    out[(long)n * INC + lane] = r;
}

// dec0 gather via graph table: per neighbor term = XW[batch[s]] * dinv[s]
__global__ void __launch_bounds__(256)
k_gather_tab(const int* __restrict__ batch, const float* __restrict__ b,
             float* __restrict__ out) {
    __shared__ float XWs[GG * HC];      // 16KB
    const int tid = threadIdx.x;
    {
        const float4* s4 = (const float4*)g_XW;
        float4* d4 = (float4*)XWs;
        for (int i = tid; i < GG * HC / 4; i += 256) d4[i] = s4[i];
    }
    __syncthreads();

    const int wid = tid >> 5;
    const int lane = tid & 31;
    const int n = blockIdx.x * 8 + wid;
    if (n >= NN) return;
    const int o = __ldg(&g_off[n]);
    const int d = __ldg(&g_degi[n]);
    const float dn = __ldg(&g_dinv[n]);

    // self term
    const int gn = __ldg(&batch[n]);
    float2 acc = *(const float2*)(XWs + gn * HC + lane * 2);
    acc.x *= dn; acc.y *= dn;

    int i = 0;
    for (; i + 2 <= d; i += 2) {
        const int s0 = __ldg(&g_csr[o + i]);
        const int s1 = __ldg(&g_csr[o + i + 1]);
        const int g0 = __ldg(&batch[s0]);
        const int g1 = __ldg(&batch[s1]);
        const float d0 = __ldg(&g_dinv[s0]);
        const float d1 = __ldg(&g_dinv[s1]);
        const float2 v0 = *(const float2*)(XWs + g0 * HC + lane * 2);
        const float2 v1 = *(const float2*)(XWs + g1 * HC + lane * 2);
        acc.x += v0.x * d0 + v1.x * d1;
        acc.y += v0.y * d0 + v1.y * d1;
    }
    if (i < d) {
        const int s = __ldg(&g_csr[o + i]);
        const int g = __ldg(&batch[s]);
        const float ds = __ldg(&g_dinv[s]);
        const float2 v = *(const float2*)(XWs + g * HC + lane * 2);
        acc.x += v.x * ds; acc.y += v.y * ds;
    }
    float2 r;
    r.x = fmaf(acc.x, dn, __ldg(&b[lane * 2]));
    r.y = fmaf(acc.y, dn, __ldg(&b[lane * 2 + 1]));
    *(float2*)(out + (long)n * HC + lane * 2) = r;
}

// ------------------------------------------------------------------
// GEMM: register-blocked 4 nodes x 8 channels per thread. blockDim=256.
// MODE 0: out = in@W + b          (conv0 after pre-aggregation)
// MODE 1: xws = (in@W)*dinv       (P payload for gather)
// ------------------------------------------------------------------
template <int KIN, int COUT, bool RELUIN, int MODE>
__global__ void __launch_bounds__(256, 3)
k_gemm(const float* __restrict__ in,
       const float* __restrict__ W,
       const float* __restrict__ b,
       float* __restrict__ dst) {
    constexpr int TPN = COUT / 8;
    constexpr int NG  = 256 / TPN;
    constexpr int NPB = NG * 4;
    constexpr int XSS = KIN + 1;

    __shared__ float Ws[KIN * COUT];
    __shared__ float bs[COUT];
    __shared__ float xs[NPB * XSS];

    const int tid = threadIdx.x;
    const int n0 = blockIdx.x * NPB;

    {
        const float4* W4 = (const float4*)W;
        float4* Ws4 = (float4*)Ws;
#pragma unroll
        for (int i = tid; i < KIN * COUT / 4; i += 256) Ws4[i] = W4[i];
    }
    if (tid < COUT) bs[tid] = (MODE == 0) ? b[tid] : 0.f;

    {
        constexpr int QPR = KIN / 4;
        constexpr int NQ = NPB * QPR;
        for (int i = tid; i < NQ; i += 256) {
            const int row = i / QPR;
            const int qc = i % QPR;
            float4 v = make_float4(0.f, 0.f, 0.f, 0.f);
            if (n0 + row < NN) {
                v = *(const float4*)(in + (long)(n0 + row) * KIN + qc * 4);
                if (RELUIN) {
                    v.x = fmaxf(v.x, 0.f); v.y = fmaxf(v.y, 0.f);
                    v.z = fmaxf(v.z, 0.f); v.w = fmaxf(v.w, 0.f);
                }
            }
            float* p = xs + row * XSS + qc * 4;
            p[0] = v.x; p[1] = v.y; p[2] = v.z; p[3] = v.w;
        }
    }
    __syncthreads();

    const int tc = tid % TPN;
    const int ng = tid / TPN;
    const int c0 = tc * 8;
    const int nb = ng * 4;

    float acc[4][8];
#pragma unroll
    for (int j = 0; j < 4; j++)
#pragma unroll
        for (int m = 0; m < 8; m++) acc[j][m] = 0.f;

    const float4* Ws4 = (const float4*)Ws;
#pragma unroll 8
    for (int k = 0; k < KIN; k++) {
        const float4 w0 = Ws4[(k * COUT + c0) >> 2];
        const float4 w1 = Ws4[((k * COUT + c0) >> 2) + 1];
        float xv[4];
#pragma unroll
        for (int j = 0; j < 4; j++) xv[j] = xs[(nb + j) * XSS + k];
#pragma unroll
        for (int j = 0; j < 4; j++) {
            acc[j][0] = fmaf(xv[j], w0.x, acc[j][0]);
            acc[j][1] = fmaf(xv[j], w0.y, acc[j][1]);
            acc[j][2] = fmaf(xv[j], w0.z, acc[j][2]);
            acc[j][3] = fmaf(xv[j], w0.w, acc[j][3]);
            acc[j][4] = fmaf(xv[j], w1.x, acc[j][4]);
            acc[j][5] = fmaf(xv[j], w1.y, acc[j][5]);
            acc[j][6] = fmaf(xv[j], w1.z, acc[j][6]);
            acc[j][7] = fmaf(xv[j], w1.w, acc[j][7]);
        }
    }

#pragma unroll
    for (int j = 0; j < 4; j++) {
        const int n = n0 + nb + j;
        if (n >= NN) break;
        float4 o0, o1;
        if (MODE == 1) {
            const float d = g_dinv[n];
            o0.x = acc[j][0] * d; o0.y = acc[j][1] * d;
            o0.z = acc[j][2] * d; o0.w = acc[j][3] * d;
            o1.x = acc[j][4] * d; o1.y = acc[j][5] * d;
            o1.z = acc[j][6] * d; o1.w = acc[j][7] * d;
        } else {
            o0.x = acc[j][0] + bs[c0 + 0]; o0.y = acc[j][1] + bs[c0 + 1];
            o0.z = acc[j][2] + bs[c0 + 2]; o0.w = acc[j][3] + bs[c0 + 3];
            o1.x = acc[j][4] + bs[c0 + 4]; o1.y = acc[j][5] + bs[c0 + 5];
            o1.z = acc[j][6] + bs[c0 + 6]; o1.w = acc[j][7] + bs[c0 + 7];
        }
        float* op = dst + (long)n * COUT + c0;
        *(float4*)(op) = o0; *(float4*)(op + 4) = o1;
    }
}

// ------------------------------------------------------------------
// Pool: register run-length accumulation over sorted batch ids.
// ------------------------------------------------------------------
__global__ void k_pool(const int* __restrict__ batch, const float* __restrict__ h) {
    const int tid = threadIdx.x;
    const int c = tid % HC;
    const int r = tid / HC;
    float acc = 0.f;
    float cacc = 0.f;
    int curg = -1;
    for (int n = blockIdx.x * 4 + r; n < NN; n += gridDim.x * 4) {
        const int g = __ldg(&batch[n]);
        if (g != curg) {
            if (curg >= 0) {
                atomicAdd(&g_sums[curg * HC + c], acc);
                if (c == 0) atomicAdd(&g_cnt[curg], cacc);
            }
            acc = 0.f; cacc = 0.f; curg = g;
        }
        acc += fmaxf(h[(long)n * HC + c], 0.f);
        cacc += 1.f;
    }
    if (curg >= 0) {
        atomicAdd(&g_sums[curg * HC + c], acc);
        if (c == 0) atomicAdd(&g_cnt[curg], cacc);
    }
}

// z = (sums/cnt) @ W_proj + b_proj  -> g_z and d_out tail
__global__ void __launch_bounds__(1024)
k_zproj(const float* __restrict__ Wp, const float* __restrict__ bp,
        float* __restrict__ zout) {
    const int tid = threadIdx.x;           // 0..1023
    const int g = tid / LC, l = tid % LC;
    const float inv = 1.0f / fmaxf(g_cnt[g], 1.0f);
    float s = bp[l];
#pragma unroll
    for (int k = 0; k < HC; k++)
        s = fmaf(g_sums[g * HC + k] * inv, Wp[k * LC + l], s);
    g_z[g * LC + l] = s;
    zout[g * LC + l] = s;
}

// ------------------------------------------------------------------
// Graph-space decoder head: D = relu(z@Wdp + bdp); XW = D @ W_dec0
// ------------------------------------------------------------------
__global__ void __launch_bounds__(1024)
k_graphdec(const float* __restrict__ Wdp,
           const float* __restrict__ bdp,
           const float* __restrict__ Wd0) {
    __shared__ float zs[GG * LC];
    __shared__ float Ds[GG * HC];
    __shared__ float Wd0s[HC * HC];
    const int tid = threadIdx.x;

    for (int i = tid; i < GG * LC; i += 1024) zs[i] = g_z[i];
    for (int i = tid; i < HC * HC; i += 1024) Wd0s[i] = Wd0[i];
    __syncthreads();

    for (int i = tid; i < GG * HC; i += 1024) {
        const int g = i / HC, c = i % HC;
        float s = bdp[c];
#pragma unroll
        for (int k = 0; k < LC; k++) s = fmaf(zs[g * LC + k], Wdp[k * HC + c], s);
        Ds[i] = fmaxf(s, 0.f);
    }
    __syncthreads();

    for (int i = tid; i < GG * HC; i += 1024) {
        const int g = i / HC, c = i % HC;
        float s = 0.f;
#pragma unroll 16
        for (int k = 0; k < HC; k++) s = fmaf(Ds[g * HC + k], Wd0s[k * HC + c], s);
        g_XW[i] = s;
    }
}

// ------------------------------------------------------------------
extern "C" void kernel_launch(void* const* d_in, const int* in_sizes, int n_in,
                              void* d_out, int out_size) {
    const float* x       = (const float*)d_in[0];
    const int*   ei      = (const int*)  d_in[1];
    const int*   batch   = (const int*)  d_in[2];
    const float* W_enc0  = (const float*)d_in[3];
    const float* b_enc0  = (const float*)d_in[4];
    const float* W_enc1  = (const float*)d_in[5];
    const float* b_enc1  = (const float*)d_in[6];
    const float* W_enc2  = (const float*)d_in[7];
    const float* b_enc2  = (const float*)d_in[8];
    const float* W_proj  = (const float*)d_in[9];
    const float* b_proj  = (const float*)d_in[10];
    const float* W_decp  = (const float*)d_in[11];
    const float* b_decp  = (const float*)d_in[12];
    const float* W_dec0  = (const float*)d_in[13];
    const float* b_dec0  = (const float*)d_in[14];
    const float* W_dec1  = (const float*)d_in[15];
    const float* b_dec1  = (const float*)d_in[16];

    float* out  = (float*)d_out;
    float* xrec = out;             // [NN, INC]
    float* zout = out + NN * INC;  // [GG, LC]

    float *p_xws, *p_buf0, *p_buf1;
    cudaGetSymbolAddress((void**)&p_xws,  g_xws);
    cudaGetSymbolAddress((void**)&p_buf0, g_buf0);
    cudaGetSymbolAddress((void**)&p_buf1, g_buf1);

    const int TB = 256;
    const int gN    = (NN + TB - 1) / TB;
    const int gE    = (EE + TB - 1) / TB;
    const int gA64  = (NN + 127) / 128;     // GEMM COUT=64
    const int gA32  = (NN + 255) / 256;     // GEMM COUT=32
    const int gN8   = (NN * 8 + TB - 1) / TB;
    const int gW    = (NN + 7) / 8;         // gathers: 8 nodes/block

    // ---- degree, CSR build, dinv ----
    k_init<<<gN, TB>>>();
    k_count<<<gE, TB>>>(ei);
    k_scan1<<<NB1, 1024>>>();
    k_scan2<<<1, 128>>>();
    k_scan3<<<NB1, 1024>>>();
    k_fill<<<gE, TB>>>(ei);

    // ---- conv0 (aggregate in input space, then GEMM) ----
    k_P0<<<gN8, TB>>>(x, p_xws);
    k_gather32<false><<<gW, TB>>>(p_xws, nullptr, p_buf1);
    k_gemm<INC, HC, false, 0><<<gA64, TB>>>(p_buf1, W_enc0, b_enc0, p_buf0);

    // ---- conv1 ----
    k_gemm<HC, HC, true, 1><<<gA64, TB>>>(p_buf0, W_enc1, nullptr, p_xws);
    k_gather64<true><<<gW, TB>>>(p_xws, b_enc1, p_buf1);
    // ---- conv2 ----
    k_gemm<HC, HC, true, 1><<<gA64, TB>>>(p_buf1, W_enc2, nullptr, p_xws);
    k_gather64<true><<<gW, TB>>>(p_xws, b_enc2, p_buf0);

    // ---- pool + latent ----
    k_pool<<<592, TB>>>(batch, p_buf0);
    k_zproj<<<1, 1024>>>(W_proj, b_proj, zout);

    // ---- decoder graph-space head ----
    k_graphdec<<<1, 1024>>>(W_decp, b_decp, W_dec0);

    // ---- dec conv0 via graph table (gather, no N-wide GEMM) ----
    k_gather_tab<<<gW, TB>>>(batch, b_dec0, p_buf1);

    // ---- dec conv1 ----
    k_gemm<HC, INC, true, 1><<<gA32, TB>>>(p_buf1, W_dec1, nullptr, p_xws);
    k_gather32<true><<<gW, TB>>>(p_xws, b_dec1, xrec);
}

// round 7
// speedup vs baseline: 2.4723x; 1.0947x over previous
#include <cuda_runtime.h>
#include <math.h>

#define NN 100000
#define EE 1600000
#define INC 32
#define HC  64
#define LC  16
#define GG  64
#define NB1 98          // ceil(NN/1024) scan blocks

// ---- device scratch (static, no allocation) ----
__device__ int   g_degi[NN];
__device__ int   g_part[NN];
__device__ int   g_off[NN];
__device__ int   g_cur[NN];
__device__ int   g_csr[EE];
__device__ int   g_bsum[128];
__device__ int   g_bbase[128];
__device__ float g_dinv[NN];
__device__ float g_xws[NN * HC];    // P = xw * dinv (per-conv payload)
__device__ float g_buf0[NN * HC];
__device__ float g_buf1[NN * HC];
__device__ float g_sums[GG * HC];
__device__ float g_cnt[GG];
__device__ float g_z[GG * LC];
__device__ float g_XW[GG * HC];     // (relu(z@Wdp+b)) @ W_dec0, per graph

// ------------------------------------------------------------------
__global__ void k_init() {
    int i = blockIdx.x * blockDim.x + threadIdx.x;
    if (i < NN) g_degi[i] = 0;
    if (i < GG * HC) g_sums[i] = 0.f;
    if (i < GG) g_cnt[i] = 0.f;
}

__global__ void k_count(const int* __restrict__ ei) {
    int e = blockIdx.x * blockDim.x + threadIdx.x;
    if (e < EE) atomicAdd(&g_degi[ei[EE + e]], 1);
}

// block-level exclusive scan of degi (1024/block)
__global__ void __launch_bounds__(1024) k_scan1() {
    __shared__ int sm[1024];
    const int tid = threadIdx.x;
    const int i = blockIdx.x * 1024 + tid;
    const int v = (i < NN) ? g_degi[i] : 0;
    sm[tid] = v;
    __syncthreads();
    for (int o = 1; o < 1024; o <<= 1) {
        int t = (tid >= o) ? sm[tid - o] : 0;
        __syncthreads();
        sm[tid] += t;
        __syncthreads();
    }
    if (i < NN) g_part[i] = sm[tid] - v;          // exclusive
    if (tid == 1023) g_bsum[blockIdx.x] = sm[1023];
}

__global__ void __launch_bounds__(128) k_scan2() {
    __shared__ int sm[128];
    const int tid = threadIdx.x;
    const int v = (tid < NB1) ? g_bsum[tid] : 0;
    sm[tid] = v;
    __syncthreads();
    for (int o = 1; o < 128; o <<= 1) {
        int t = (tid >= o) ? sm[tid - o] : 0;
        __syncthreads();
        sm[tid] += t;
        __syncthreads();
    }
    g_bbase[tid] = sm[tid] - v;                   // exclusive
}

__global__ void __launch_bounds__(1024) k_scan3() {
    const int i = blockIdx.x * 1024 + threadIdx.x;
    if (i >= NN) return;
    const int o = g_part[i] + g_bbase[blockIdx.x];
    g_off[i] = o;
    g_cur[i] = o;
    g_dinv[i] = rsqrtf((float)g_degi[i] + 1.0f);
}

__global__ void k_fill(const int* __restrict__ ei) {
    int e = blockIdx.x * blockDim.x + threadIdx.x;
    if (e >= EE) return;
    const int src = __ldg(&ei[e]);
    const int dst = __ldg(&ei[EE + e]);
    const int pos = atomicAdd(&g_cur[dst], 1);
    g_csr[pos] = src;
}

// ------------------------------------------------------------------
// conv0 fused gather (quarter-warp/node, float4 row):
// out[n] = dinv[n] * ( sum_s x[s]*dinv[s]  +  x[n]*dinv[n] )
// ------------------------------------------------------------------
__global__ void __launch_bounds__(256)
k_gather32x(const float* __restrict__ x, float* __restrict__ out) {
    const int wid = threadIdx.x >> 5;
    const int lane = threadIdx.x & 31;
    const int q = lane >> 3;
    const int l8 = lane & 7;
    const int n = blockIdx.x * 32 + wid * 4 + q;
    if (n >= NN) return;
    const int o = __ldg(&g_off[n]);
    const int d = __ldg(&g_degi[n]);
    const float dn = __ldg(&g_dinv[n]);

    float4 acc = make_float4(0.f, 0.f, 0.f, 0.f);
    int i = 0;
    for (; i + 4 <= d; i += 4) {
        const int s0 = __ldg(&g_csr[o + i]);
        const int s1 = __ldg(&g_csr[o + i + 1]);
        const int s2 = __ldg(&g_csr[o + i + 2]);
        const int s3 = __ldg(&g_csr[o + i + 3]);
        const float d0 = __ldg(&g_dinv[s0]);
        const float d1 = __ldg(&g_dinv[s1]);
        const float d2 = __ldg(&g_dinv[s2]);
        const float d3 = __ldg(&g_dinv[s3]);
        const float4 v0 = *(const float4*)(x + (long)s0 * INC + l8 * 4);
        const float4 v1 = *(const float4*)(x + (long)s1 * INC + l8 * 4);
        const float4 v2 = *(const float4*)(x + (long)s2 * INC + l8 * 4);
        const float4 v3 = *(const float4*)(x + (long)s3 * INC + l8 * 4);
        acc.x = fmaf(v0.x, d0, fmaf(v1.x, d1, fmaf(v2.x, d2, fmaf(v3.x, d3, acc.x))));
        acc.y = fmaf(v0.y, d0, fmaf(v1.y, d1, fmaf(v2.y, d2, fmaf(v3.y, d3, acc.y))));
        acc.z = fmaf(v0.z, d0, fmaf(v1.z, d1, fmaf(v2.z, d2, fmaf(v3.z, d3, acc.z))));
        acc.w = fmaf(v0.w, d0, fmaf(v1.w, d1, fmaf(v2.w, d2, fmaf(v3.w, d3, acc.w))));
    }
    for (; i < d; i++) {
        const int s = __ldg(&g_csr[o + i]);
        const float ds = __ldg(&g_dinv[s]);
        const float4 v = *(const float4*)(x + (long)s * INC + l8 * 4);
        acc.x = fmaf(v.x, ds, acc.x); acc.y = fmaf(v.y, ds, acc.y);
        acc.z = fmaf(v.z, ds, acc.z); acc.w = fmaf(v.w, ds, acc.w);
    }
    const float4 xv = *(const float4*)(x + (long)n * INC + l8 * 4);
    float4 r;
    r.x = (fmaf(xv.x, dn, acc.x)) * dn;
    r.y = (fmaf(xv.y, dn, acc.y)) * dn;
    r.z = (fmaf(xv.z, dn, acc.z)) * dn;
    r.w = (fmaf(xv.w, dn, acc.w)) * dn;
    *(float4*)(out + (long)n * INC + l8 * 4) = r;
}

// ------------------------------------------------------------------
// 64-ch gather (half-warp/node, float4 row): out = dinv[n]*(sum P[s] + P[n]) + b
// ------------------------------------------------------------------
__global__ void __launch_bounds__(256)
k_gather64(const float* __restrict__ P, const float* __restrict__ b,
           float* __restrict__ out) {
    const int wid = threadIdx.x >> 5;
    const int lane = threadIdx.x & 31;
    const int h = lane >> 4;
    const int l16 = lane & 15;
    const int n = blockIdx.x * 16 + wid * 2 + h;
    if (n >= NN) return;
    const int o = __ldg(&g_off[n]);
    const int d = __ldg(&g_degi[n]);

    float4 acc = *(const float4*)(P + (long)n * HC + l16 * 4);  // self
    int i = 0;
    for (; i + 4 <= d; i += 4) {
        const int s0 = __ldg(&g_csr[o + i]);
        const int s1 = __ldg(&g_csr[o + i + 1]);
        const int s2 = __ldg(&g_csr[o + i + 2]);
        const int s3 = __ldg(&g_csr[o + i + 3]);
        const float4 v0 = *(const float4*)(P + (long)s0 * HC + l16 * 4);
        const float4 v1 = *(const float4*)(P + (long)s1 * HC + l16 * 4);
        const float4 v2 = *(const float4*)(P + (long)s2 * HC + l16 * 4);
        const float4 v3 = *(const float4*)(P + (long)s3 * HC + l16 * 4);
        acc.x += (v0.x + v1.x) + (v2.x + v3.x);
        acc.y += (v0.y + v1.y) + (v2.y + v3.y);
        acc.z += (v0.z + v1.z) + (v2.z + v3.z);
        acc.w += (v0.w + v1.w) + (v2.w + v3.w);
    }
    for (; i < d; i++) {
        const int s = __ldg(&g_csr[o + i]);
        const float4 v = *(const float4*)(P + (long)s * HC + l16 * 4);
        acc.x += v.x; acc.y += v.y; acc.z += v.z; acc.w += v.w;
    }
    const float dn = __ldg(&g_dinv[n]);
    const float4 b4 = __ldg(&((const float4*)b)[l16]);
    float4 r;
    r.x = fmaf(acc.x, dn, b4.x); r.y = fmaf(acc.y, dn, b4.y);
    r.z = fmaf(acc.z, dn, b4.z); r.w = fmaf(acc.w, dn, b4.w);
    *(float4*)(out + (long)n * HC + l16 * 4) = r;
}

// dec0 gather via graph table (half-warp/node, smem table)
__global__ void __launch_bounds__(256)
k_gather_tab(const int* __restrict__ batch, const float* __restrict__ b,
             float* __restrict__ out) {
    __shared__ float XWs[GG * HC];      // 16KB
    const int tid = threadIdx.x;
    {
        const float4* s4 = (const float4*)g_XW;
        float4* d4 = (float4*)XWs;
        for (int i = tid; i < GG * HC / 4; i += 256) d4[i] = s4[i];
    }
    __syncthreads();

    const int wid = tid >> 5;
    const int lane = tid & 31;
    const int h = lane >> 4;
    const int l16 = lane & 15;
    const int n = blockIdx.x * 16 + wid * 2 + h;
    if (n >= NN) return;
    const int o = __ldg(&g_off[n]);
    const int d = __ldg(&g_degi[n]);
    const float dn = __ldg(&g_dinv[n]);

    // self term
    const int gn = __ldg(&batch[n]);
    float4 acc = *(const float4*)(XWs + gn * HC + l16 * 4);
    acc.x *= dn; acc.y *= dn; acc.z *= dn; acc.w *= dn;

    int i = 0;
    for (; i + 2 <= d; i += 2) {
        const int s0 = __ldg(&g_csr[o + i]);
        const int s1 = __ldg(&g_csr[o + i + 1]);
        const int g0 = __ldg(&batch[s0]);
        const int g1 = __ldg(&batch[s1]);
        const float d0 = __ldg(&g_dinv[s0]);
        const float d1 = __ldg(&g_dinv[s1]);
        const float4 v0 = *(const float4*)(XWs + g0 * HC + l16 * 4);
        const float4 v1 = *(const float4*)(XWs + g1 * HC + l16 * 4);
        acc.x = fmaf(v0.x, d0, fmaf(v1.x, d1, acc.x));
        acc.y = fmaf(v0.y, d0, fmaf(v1.y, d1, acc.y));
        acc.z = fmaf(v0.z, d0, fmaf(v1.z, d1, acc.z));
        acc.w = fmaf(v0.w, d0, fmaf(v1.w, d1, acc.w));
    }
    if (i < d) {
        const int s = __ldg(&g_csr[o + i]);
        const int g = __ldg(&batch[s]);
        const float ds = __ldg(&g_dinv[s]);
        const float4 v = *(const float4*)(XWs + g * HC + l16 * 4);
        acc.x = fmaf(v.x, ds, acc.x); acc.y = fmaf(v.y, ds, acc.y);
        acc.z = fmaf(v.z, ds, acc.z); acc.w = fmaf(v.w, ds, acc.w);
    }
    const float4 b4 = __ldg(&((const float4*)b)[l16]);
    float4 r;
    r.x = fmaf(acc.x, dn, b4.x); r.y = fmaf(acc.y, dn, b4.y);
    r.z = fmaf(acc.z, dn, b4.z); r.w = fmaf(acc.w, dn, b4.w);
    *(float4*)(out + (long)n * HC + l16 * 4) = r;
}

// 32-ch payload gather (quarter-warp/node): out = dinv[n]*(sum P[s] + P[n]) + b
__global__ void __launch_bounds__(256)
k_gather32p(const float* __restrict__ P, const float* __restrict__ b,
            float* __restrict__ out) {
    const int wid = threadIdx.x >> 5;
    const int lane = threadIdx.x & 31;
    const int q = lane >> 3;
    const int l8 = lane & 7;
    const int n = blockIdx.x * 32 + wid * 4 + q;
    if (n >= NN) return;
    const int o = __ldg(&g_off[n]);
    const int d = __ldg(&g_degi[n]);

    float4 acc = *(const float4*)(P + (long)n * INC + l8 * 4);  // self
    int i = 0;
    for (; i + 4 <= d; i += 4) {
        const int s0 = __ldg(&g_csr[o + i]);
        const int s1 = __ldg(&g_csr[o + i + 1]);
        const int s2 = __ldg(&g_csr[o + i + 2]);
        const int s3 = __ldg(&g_csr[o + i + 3]);
        const float4 v0 = *(const float4*)(P + (long)s0 * INC + l8 * 4);
        const float4 v1 = *(const float4*)(P + (long)s1 * INC + l8 * 4);
        const float4 v2 = *(const float4*)(P + (long)s2 * INC + l8 * 4);
        const float4 v3 = *(const float4*)(P + (long)s3 * INC + l8 * 4);
        acc.x += (v0.x + v1.x) + (v2.x + v3.x);
        acc.y += (v0.y + v1.y) + (v2.y + v3.y);
        acc.z += (v0.z + v1.z) + (v2.z + v3.z);
        acc.w += (v0.w + v1.w) + (v2.w + v3.w);
    }
    for (; i < d; i++) {
        const int s = __ldg(&g_csr[o + i]);
        const float4 v = *(const float4*)(P + (long)s * INC + l8 * 4);
        acc.x += v.x; acc.y += v.y; acc.z += v.z; acc.w += v.w;
    }
    const float dn = __ldg(&g_dinv[n]);
    const float4 b4 = __ldg(&((const float4*)b)[l8]);
    float4 r;
    r.x = fmaf(acc.x, dn, b4.x); r.y = fmaf(acc.y, dn, b4.y);
    r.z = fmaf(acc.z, dn, b4.z); r.w = fmaf(acc.w, dn, b4.w);
    *(float4*)(out + (long)n * INC + l8 * 4) = r;
}

// ------------------------------------------------------------------
// GEMM: register-blocked 4 nodes x 8 channels per thread. blockDim=256.
// MODE 0: out = in@W + b          (conv0 after pre-aggregation)
// MODE 1: xws = (in@W)*dinv       (P payload for gather)
// ------------------------------------------------------------------
template <int KIN, int COUT, bool RELUIN, int MODE>
__global__ void __launch_bounds__(256, 3)
k_gemm(const float* __restrict__ in,
       const float* __restrict__ W,
       const float* __restrict__ b,
       float* __restrict__ dst) {
    constexpr int TPN = COUT / 8;
    constexpr int NG  = 256 / TPN;
    constexpr int NPB = NG * 4;
    constexpr int XSS = KIN + 1;

    __shared__ float Ws[KIN * COUT];
    __shared__ float bs[COUT];
    __shared__ float xs[NPB * XSS];

    const int tid = threadIdx.x;
    const int n0 = blockIdx.x * NPB;

    {
        const float4* W4 = (const float4*)W;
        float4* Ws4 = (float4*)Ws;
#pragma unroll
        for (int i = tid; i < KIN * COUT / 4; i += 256) Ws4[i] = W4[i];
    }
    if (tid < COUT) bs[tid] = (MODE == 0) ? b[tid] : 0.f;

    {
        constexpr int QPR = KIN / 4;
        constexpr int NQ = NPB * QPR;
        for (int i = tid; i < NQ; i += 256) {
            const int row = i / QPR;
            const int qc = i % QPR;
            float4 v = make_float4(0.f, 0.f, 0.f, 0.f);
            if (n0 + row < NN) {
                v = *(const float4*)(in + (long)(n0 + row) * KIN + qc * 4);
                if (RELUIN) {
                    v.x = fmaxf(v.x, 0.f); v.y = fmaxf(v.y, 0.f);
                    v.z = fmaxf(v.z, 0.f); v.w = fmaxf(v.w, 0.f);
                }
            }
            float* p = xs + row * XSS + qc * 4;
            p[0] = v.x; p[1] = v.y; p[2] = v.z; p[3] = v.w;
        }
    }
    __syncthreads();

    const int tc = tid % TPN;
    const int ng = tid / TPN;
    const int c0 = tc * 8;
    const int nb = ng * 4;

    float acc[4][8];
#pragma unroll
    for (int j = 0; j < 4; j++)
#pragma unroll
        for (int m = 0; m < 8; m++) acc[j][m] = 0.f;

    const float4* Ws4 = (const float4*)Ws;
#pragma unroll 8
    for (int k = 0; k < KIN; k++) {
        const float4 w0 = Ws4[(k * COUT + c0) >> 2];
        const float4 w1 = Ws4[((k * COUT + c0) >> 2) + 1];
        float xv[4];
#pragma unroll
        for (int j = 0; j < 4; j++) xv[j] = xs[(nb + j) * XSS + k];
#pragma unroll
        for (int j = 0; j < 4; j++) {
            acc[j][0] = fmaf(xv[j], w0.x, acc[j][0]);
            acc[j][1] = fmaf(xv[j], w0.y, acc[j][1]);
            acc[j][2] = fmaf(xv[j], w0.z, acc[j][2]);
            acc[j][3] = fmaf(xv[j], w0.w, acc[j][3]);
            acc[j][4] = fmaf(xv[j], w1.x, acc[j][4]);
            acc[j][5] = fmaf(xv[j], w1.y, acc[j][5]);
            acc[j][6] = fmaf(xv[j], w1.z, acc[j][6]);
            acc[j][7] = fmaf(xv[j], w1.w, acc[j][7]);
        }
    }

#pragma unroll
    for (int j = 0; j < 4; j++) {
        const int n = n0 + nb + j;
        if (n >= NN) break;
        float4 o0, o1;
        if (MODE == 1) {
            const float d = g_dinv[n];
            o0.x = acc[j][0] * d; o0.y = acc[j][1] * d;
            o0.z = acc[j][2] * d; o0.w = acc[j][3] * d;
            o1.x = acc[j][4] * d; o1.y = acc[j][5] * d;
            o1.z = acc[j][6] * d; o1.w = acc[j][7] * d;
        } else {
            o0.x = acc[j][0] + bs[c0 + 0]; o0.y = acc[j][1] + bs[c0 + 1];
            o0.z = acc[j][2] + bs[c0 + 2]; o0.w = acc[j][3] + bs[c0 + 3];
            o1.x = acc[j][4] + bs[c0 + 4]; o1.y = acc[j][5] + bs[c0 + 5];
            o1.z = acc[j][6] + bs[c0 + 6]; o1.w = acc[j][7] + bs[c0 + 7];
        }
        float* op = dst + (long)n * COUT + c0;
        *(float4*)(op) = o0; *(float4*)(op + 4) = o1;
    }
}

// ------------------------------------------------------------------
// Pool: register run-length accumulation over sorted batch ids.
// ------------------------------------------------------------------
__global__ void k_pool(const int* __restrict__ batch, const float* __restrict__ h) {
    const int tid = threadIdx.x;
    const int c = tid % HC;
    const int r = tid / HC;
    float acc = 0.f;
    float cacc = 0.f;
    int curg = -1;
    for (int n = blockIdx.x * 4 + r; n < NN; n += gridDim.x * 4) {
        const int g = __ldg(&batch[n]);
        if (g != curg) {
            if (curg >= 0) {
                atomicAdd(&g_sums[curg * HC + c], acc);
                if (c == 0) atomicAdd(&g_cnt[curg], cacc);
            }
            acc = 0.f; cacc = 0.f; curg = g;
        }
        acc += fmaxf(h[(long)n * HC + c], 0.f);
        cacc += 1.f;
    }
    if (curg >= 0) {
        atomicAdd(&g_sums[curg * HC + c], acc);
        if (c == 0) atomicAdd(&g_cnt[curg], cacc);
    }
}

// z = (sums/cnt) @ W_proj + b_proj  -> g_z and d_out tail
__global__ void __launch_bounds__(1024)
k_zproj(const float* __restrict__ Wp, const float* __restrict__ bp,
        float* __restrict__ zout) {
    const int tid = threadIdx.x;           // 0..1023
    const int g = tid / LC, l = tid % LC;
    const float inv = 1.0f / fmaxf(g_cnt[g], 1.0f);
    float s = bp[l];
#pragma unroll
    for (int k = 0; k < HC; k++)
        s = fmaf(g_sums[g * HC + k] * inv, Wp[k * LC + l], s);
    g_z[g * LC + l] = s;
    zout[g * LC + l] = s;
}

// ------------------------------------------------------------------
// Graph-space decoder head: D = relu(z@Wdp + bdp); XW = D @ W_dec0
// ------------------------------------------------------------------
__global__ void __launch_bounds__(1024)
k_graphdec(const float* __restrict__ Wdp,
           const float* __restrict__ bdp,
           const float* __restrict__ Wd0) {
    __shared__ float zs[GG * LC];
    __shared__ float Ds[GG * HC];
    __shared__ float Wd0s[HC * HC];
    const int tid = threadIdx.x;

    for (int i = tid; i < GG * LC; i += 1024) zs[i] = g_z[i];
    for (int i = tid; i < HC * HC; i += 1024) Wd0s[i] = Wd0[i];
    __syncthreads();

    for (int i = tid; i < GG * HC; i += 1024) {
        const int g = i / HC, c = i % HC;
        float s = bdp[c];
#pragma unroll
        for (int k = 0; k < LC; k++) s = fmaf(zs[g * LC + k], Wdp[k * HC + c], s);
        Ds[i] = fmaxf(s, 0.f);
    }
    __syncthreads();

    for (int i = tid; i < GG * HC; i += 1024) {
        const int g = i / HC, c = i % HC;
        float s = 0.f;
#pragma unroll 16
        for (int k = 0; k < HC; k++) s = fmaf(Ds[g * HC + k], Wd0s[k * HC + c], s);
        g_XW[i] = s;
    }
}

// ------------------------------------------------------------------
extern "C" void kernel_launch(void* const* d_in, const int* in_sizes, int n_in,
                              void* d_out, int out_size) {
    const float* x       = (const float*)d_in[0];
    const int*   ei      = (const int*)  d_in[1];
    const int*   batch   = (const int*)  d_in[2];
    const float* W_enc0  = (const float*)d_in[3];
    const float* b_enc0  = (const float*)d_in[4];
    const float* W_enc1  = (const float*)d_in[5];
    const float* b_enc1  = (const float*)d_in[6];
    const float* W_enc2  = (const float*)d_in[7];
    const float* b_enc2  = (const float*)d_in[8];
    const float* W_proj  = (const float*)d_in[9];
    const float* b_proj  = (const float*)d_in[10];
    const float* W_decp  = (const float*)d_in[11];
    const float* b_decp  = (const float*)d_in[12];
    const float* W_dec0  = (const float*)d_in[13];
    const float* b_dec0  = (const float*)d_in[14];
    const float* W_dec1  = (const float*)d_in[15];
    const float* b_dec1  = (const float*)d_in[16];

    float* out  = (float*)d_out;
    float* xrec = out;             // [NN, INC]
    float* zout = out + NN * INC;  // [GG, LC]

    float *p_xws, *p_buf0, *p_buf1;
    cudaGetSymbolAddress((void**)&p_xws,  g_xws);
    cudaGetSymbolAddress((void**)&p_buf0, g_buf0);
    cudaGetSymbolAddress((void**)&p_buf1, g_buf1);

    const int TB = 256;
    const int gN    = (NN + TB - 1) / TB;
    const int gE    = (EE + TB - 1) / TB;
    const int gA64  = (NN + 127) / 128;     // GEMM COUT=64
    const int gA32  = (NN + 255) / 256;     // GEMM COUT=32
    const int gG64  = (NN + 15) / 16;       // 64-ch gathers: 16 nodes/block
    const int gG32  = (NN + 31) / 32;       // 32-ch gathers: 32 nodes/block

    // ---- degree, CSR build, dinv ----
    k_init<<<gN, TB>>>();
    k_count<<<gE, TB>>>(ei);
    k_scan1<<<NB1, 1024>>>();
    k_scan2<<<1, 128>>>();
    k_scan3<<<NB1, 1024>>>();
    k_fill<<<gE, TB>>>(ei);

    // ---- conv0 (fused aggregate in input space, then GEMM) ----
    k_gather32x<<<gG32, TB>>>(x, p_buf1);
    k_gemm<INC, HC, false, 0><<<gA64, TB>>>(p_buf1, W_enc0, b_enc0, p_buf0);

    // ---- conv1 ----
    k_gemm<HC, HC, true, 1><<<gA64, TB>>>(p_buf0, W_enc1, nullptr, p_xws);
    k_gather64<<<gG64, TB>>>(p_xws, b_enc1, p_buf1);
    // ---- conv2 ----
    k_gemm<HC, HC, true, 1><<<gA64, TB>>>(p_buf1, W_enc2, nullptr, p_xws);
    k_gather64<<<gG64, TB>>>(p_xws, b_enc2, p_buf0);

    // ---- pool + latent ----
    k_pool<<<592, TB>>>(batch, p_buf0);
    k_zproj<<<1, 1024>>>(W_proj, b_proj, zout);

    // ---- decoder graph-space head ----
    k_graphdec<<<1, 1024>>>(W_decp, b_decp, W_dec0);

    // ---- dec conv0 via graph table (gather, no N-wide GEMM) ----
    k_gather_tab<<<gG64, TB>>>(batch, b_dec0, p_buf1);

    // ---- dec conv1 ----
    k_gemm<HC, INC, true, 1><<<gA32, TB>>>(p_buf1, W_dec1, nullptr, p_xws);
    k_gather32p<<<gG32, TB>>>(p_xws, b_dec1, xrec);
}

// round 8
// speedup vs baseline: 2.5588x; 1.0350x over previous
#include <cuda_runtime.h>
#include <cuda_fp16.h>
#include <math.h>

#define NN 100000
#define EE 1600000
#define INC 32
#define HC  64
#define LC  16
#define GG  64
#define NB1 98          // ceil(NN/1024) scan blocks

// ---- device scratch (static, no allocation) ----
__device__ int   g_degi[NN];
__device__ int   g_part[NN];
__device__ int   g_off[NN];
__device__ int   g_cur[NN];
__device__ int   g_csr[EE];
__device__ int   g_bsum[128];
__device__ float g_dinv[NN];
__device__ float g_xws[NN * HC];    // payload: fp32 rows OR packed half rows
__device__ float g_buf0[NN * HC];
__device__ float g_buf1[NN * HC];
__device__ float g_sums[GG * HC];
__device__ float g_cnt[GG];
__device__ float g_XW[GG * HC];     // (relu(z@Wdp+b)) @ W_dec0, per graph

// ------------------------------------------------------------------
__global__ void k_init() {
    int i = blockIdx.x * blockDim.x + threadIdx.x;
    if (i < NN) g_degi[i] = 0;
    if (i < GG * HC) g_sums[i] = 0.f;
    if (i < GG) g_cnt[i] = 0.f;
}

__global__ void k_count(const int* __restrict__ ei) {
    int e = blockIdx.x * blockDim.x + threadIdx.x;
    if (e < EE) atomicAdd(&g_degi[ei[EE + e]], 1);
}

// block-level exclusive scan of degi (1024/block)
__global__ void __launch_bounds__(1024) k_scan1() {
    __shared__ int sm[1024];
    const int tid = threadIdx.x;
    const int i = blockIdx.x * 1024 + tid;
    const int v = (i < NN) ? g_degi[i] : 0;
    sm[tid] = v;
    __syncthreads();
    for (int o = 1; o < 1024; o <<= 1) {
        int t = (tid >= o) ? sm[tid - o] : 0;
        __syncthreads();
        sm[tid] += t;
        __syncthreads();
    }
    if (i < NN) g_part[i] = sm[tid] - v;          // exclusive
    if (tid == 1023) g_bsum[blockIdx.x] = sm[1023];
}

// scan of block sums (redundant per block, in smem) + finalize offsets/dinv
__global__ void __launch_bounds__(1024) k_scan3() {
    __shared__ int sb[128];
    __shared__ int sv[128];
    const int tid = threadIdx.x;
    if (tid < 128) {
        int v = (tid < NB1) ? g_bsum[tid] : 0;
        sb[tid] = v; sv[tid] = v;
    }
    __syncthreads();
    for (int o = 1; o < 128; o <<= 1) {
        int t = 0;
        if (tid >= o && tid < 128) t = sb[tid - o];
        __syncthreads();
        if (tid < 128) sb[tid] += t;
        __syncthreads();
    }
    const int i = blockIdx.x * 1024 + tid;
    if (i >= NN) return;
    const int base = sb[blockIdx.x] - sv[blockIdx.x];   // exclusive block base
    const int o = g_part[i] + base;
    g_off[i] = o;
    g_cur[i] = o;
    g_dinv[i] = rsqrtf((float)g_degi[i] + 1.0f);
}

__global__ void k_fill(const int* __restrict__ ei) {
    int e = blockIdx.x * blockDim.x + threadIdx.x;
    if (e >= EE) return;
    const int src = __ldg(&ei[e]);
    const int dst = __ldg(&ei[EE + e]);
    const int pos = atomicAdd(&g_cur[dst], 1);
    g_csr[pos] = src;
}

// ------------------------------------------------------------------
// conv0 fused gather (quarter-warp/node, float4 row):
// out[n] = dinv[n] * ( sum_s x[s]*dinv[s]  +  x[n]*dinv[n] )
// ------------------------------------------------------------------
__global__ void __launch_bounds__(256)
k_gather32x(const float* __restrict__ x, float* __restrict__ out) {
    const int wid = threadIdx.x >> 5;
    const int lane = threadIdx.x & 31;
    const int q = lane >> 3;
    const int l8 = lane & 7;
    const int n = blockIdx.x * 32 + wid * 4 + q;
    if (n >= NN) return;
    const int o = __ldg(&g_off[n]);
    const int d = __ldg(&g_degi[n]);
    const float dn = __ldg(&g_dinv[n]);

    float4 acc = make_float4(0.f, 0.f, 0.f, 0.f);
    int i = 0;
    for (; i + 4 <= d; i += 4) {
        const int s0 = __ldg(&g_csr[o + i]);
        const int s1 = __ldg(&g_csr[o + i + 1]);
        const int s2 = __ldg(&g_csr[o + i + 2]);
        const int s3 = __ldg(&g_csr[o + i + 3]);
        const float d0 = __ldg(&g_dinv[s0]);
        const float d1 = __ldg(&g_dinv[s1]);
        const float d2 = __ldg(&g_dinv[s2]);
        const float d3 = __ldg(&g_dinv[s3]);
        const float4 v0 = *(const float4*)(x + (long)s0 * INC + l8 * 4);
        const float4 v1 = *(const float4*)(x + (long)s1 * INC + l8 * 4);
        const float4 v2 = *(const float4*)(x + (long)s2 * INC + l8 * 4);
        const float4 v3 = *(const float4*)(x + (long)s3 * INC + l8 * 4);
        acc.x = fmaf(v0.x, d0, fmaf(v1.x, d1, fmaf(v2.x, d2, fmaf(v3.x, d3, acc.x))));
        acc.y = fmaf(v0.y, d0, fmaf(v1.y, d1, fmaf(v2.y, d2, fmaf(v3.y, d3, acc.y))));
        acc.z = fmaf(v0.z, d0, fmaf(v1.z, d1, fmaf(v2.z, d2, fmaf(v3.z, d3, acc.z))));
        acc.w = fmaf(v0.w, d0, fmaf(v1.w, d1, fmaf(v2.w, d2, fmaf(v3.w, d3, acc.w))));
    }
    for (; i < d; i++) {
        const int s = __ldg(&g_csr[o + i]);
        const float ds = __ldg(&g_dinv[s]);
        const float4 v = *(const float4*)(x + (long)s * INC + l8 * 4);
        acc.x = fmaf(v.x, ds, acc.x); acc.y = fmaf(v.y, ds, acc.y);
        acc.z = fmaf(v.z, ds, acc.z); acc.w = fmaf(v.w, ds, acc.w);
    }
    const float4 xv = *(const float4*)(x + (long)n * INC + l8 * 4);
    float4 r;
    r.x = (fmaf(xv.x, dn, acc.x)) * dn;
    r.y = (fmaf(xv.y, dn, acc.y)) * dn;
    r.z = (fmaf(xv.z, dn, acc.z)) * dn;
    r.w = (fmaf(xv.w, dn, acc.w)) * dn;
    *(float4*)(out + (long)n * INC + l8 * 4) = r;
}

// ------------------------------------------------------------------
// 64-ch fp16-payload gather (quarter-warp/node, uint4 = 8 halves):
// out = dinv[n]*(sum P[s] + P[n]) + b     (fp32 accumulate)
// ------------------------------------------------------------------
__global__ void __launch_bounds__(256)
k_gather64h(const __half* __restrict__ Ph, const float* __restrict__ b,
            float* __restrict__ out) {
    const int wid = threadIdx.x >> 5;
    const int lane = threadIdx.x & 31;
    const int q = lane >> 3;
    const int l8 = lane & 7;
    const int n = blockIdx.x * 32 + wid * 4 + q;
    if (n >= NN) return;
    const int o = __ldg(&g_off[n]);
    const int d = __ldg(&g_degi[n]);

    float acc[8];
    {
        uint4 u = *(const uint4*)(Ph + (long)n * HC + l8 * 8);
        const __half2* h = (const __half2*)&u;
#pragma unroll
        for (int m = 0; m < 4; m++) {
            float2 f = __half22float2(h[m]);
            acc[2 * m] = f.x; acc[2 * m + 1] = f.y;
        }
    }
    int i = 0;
    for (; i + 4 <= d; i += 4) {
        const int s0 = __ldg(&g_csr[o + i]);
        const int s1 = __ldg(&g_csr[o + i + 1]);
        const int s2 = __ldg(&g_csr[o + i + 2]);
        const int s3 = __ldg(&g_csr[o + i + 3]);
        const uint4 u0 = *(const uint4*)(Ph + (long)s0 * HC + l8 * 8);
        const uint4 u1 = *(const uint4*)(Ph + (long)s1 * HC + l8 * 8);
        const uint4 u2 = *(const uint4*)(Ph + (long)s2 * HC + l8 * 8);
        const uint4 u3 = *(const uint4*)(Ph + (long)s3 * HC + l8 * 8);
        const __half2* h0 = (const __half2*)&u0;
        const __half2* h1 = (const __half2*)&u1;
        const __half2* h2 = (const __half2*)&u2;
        const __half2* h3 = (const __half2*)&u3;
#pragma unroll
        for (int m = 0; m < 4; m++) {
            float2 f0 = __half22float2(h0[m]);
            float2 f1 = __half22float2(h1[m]);
            float2 f2 = __half22float2(h2[m]);
            float2 f3 = __half22float2(h3[m]);
            acc[2 * m]     += (f0.x + f1.x) + (f2.x + f3.x);
            acc[2 * m + 1] += (f0.y + f1.y) + (f2.y + f3.y);
        }
    }
    for (; i < d; i++) {
        const int s = __ldg(&g_csr[o + i]);
        const uint4 u = *(const uint4*)(Ph + (long)s * HC + l8 * 8);
        const __half2* h = (const __half2*)&u;
#pragma unroll
        for (int m = 0; m < 4; m++) {
            float2 f = __half22float2(h[m]);
            acc[2 * m] += f.x; acc[2 * m + 1] += f.y;
        }
    }
    const float dn = __ldg(&g_dinv[n]);
    const float4 bA = *(const float4*)(b + l8 * 8);
    const float4 bB = *(const float4*)(b + l8 * 8 + 4);
    float4 rA, rB;
    rA.x = fmaf(acc[0], dn, bA.x); rA.y = fmaf(acc[1], dn, bA.y);
    rA.z = fmaf(acc[2], dn, bA.z); rA.w = fmaf(acc[3], dn, bA.w);
    rB.x = fmaf(acc[4], dn, bB.x); rB.y = fmaf(acc[5], dn, bB.y);
    rB.z = fmaf(acc[6], dn, bB.z); rB.w = fmaf(acc[7], dn, bB.w);
    float* op = out + (long)n * HC + l8 * 8;
    *(float4*)(op) = rA; *(float4*)(op + 4) = rB;
}

// dec0 gather via graph table (half-warp/node, smem table, fp32)
__global__ void __launch_bounds__(256)
k_gather_tab(const int* __restrict__ batch, const float* __restrict__ b,
             float* __restrict__ out) {
    __shared__ float XWs[GG * HC];      // 16KB
    const int tid = threadIdx.x;
    {
        const float4* s4 = (const float4*)g_XW;
        float4* d4 = (float4*)XWs;
        for (int i = tid; i < GG * HC / 4; i += 256) d4[i] = s4[i];
    }
    __syncthreads();

    const int wid = tid >> 5;
    const int lane = tid & 31;
    const int h = lane >> 4;
    const int l16 = lane & 15;
    const int n = blockIdx.x * 16 + wid * 2 + h;
    if (n >= NN) return;
    const int o = __ldg(&g_off[n]);
    const int d = __ldg(&g_degi[n]);
    const float dn = __ldg(&g_dinv[n]);

    const int gn = __ldg(&batch[n]);
    float4 acc = *(const float4*)(XWs + gn * HC + l16 * 4);
    acc.x *= dn; acc.y *= dn; acc.z *= dn; acc.w *= dn;

    int i = 0;
    for (; i + 2 <= d; i += 2) {
        const int s0 = __ldg(&g_csr[o + i]);
        const int s1 = __ldg(&g_csr[o + i + 1]);
        const int g0 = __ldg(&batch[s0]);
        const int g1 = __ldg(&batch[s1]);
        const float d0 = __ldg(&g_dinv[s0]);
        const float d1 = __ldg(&g_dinv[s1]);
        const float4 v0 = *(const float4*)(XWs + g0 * HC + l16 * 4);
        const float4 v1 = *(const float4*)(XWs + g1 * HC + l16 * 4);
        acc.x = fmaf(v0.x, d0, fmaf(v1.x, d1, acc.x));
        acc.y = fmaf(v0.y, d0, fmaf(v1.y, d1, acc.y));
        acc.z = fmaf(v0.z, d0, fmaf(v1.z, d1, acc.z));
        acc.w = fmaf(v0.w, d0, fmaf(v1.w, d1, acc.w));
    }
    if (i < d) {
        const int s = __ldg(&g_csr[o + i]);
        const int g = __ldg(&batch[s]);
        const float ds = __ldg(&g_dinv[s]);
        const float4 v = *(const float4*)(XWs + g * HC + l16 * 4);
        acc.x = fmaf(v.x, ds, acc.x); acc.y = fmaf(v.y, ds, acc.y);
        acc.z = fmaf(v.z, ds, acc.z); acc.w = fmaf(v.w, ds, acc.w);
    }
    const float4 b4 = __ldg(&((const float4*)b)[l16]);
    float4 r;
    r.x = fmaf(acc.x, dn, b4.x); r.y = fmaf(acc.y, dn, b4.y);
    r.z = fmaf(acc.z, dn, b4.z); r.w = fmaf(acc.w, dn, b4.w);
    *(float4*)(out + (long)n * HC + l16 * 4) = r;
}

// 32-ch fp32 payload gather (quarter-warp/node): out = dinv[n]*(sum P[s]+P[n])+b
__global__ void __launch_bounds__(256)
k_gather32p(const float* __restrict__ P, const float* __restrict__ b,
            float* __restrict__ out) {
    const int wid = threadIdx.x >> 5;
    const int lane = threadIdx.x & 31;
    const int q = lane >> 3;
    const int l8 = lane & 7;
    const int n = blockIdx.x * 32 + wid * 4 + q;
    if (n >= NN) return;
    const int o = __ldg(&g_off[n]);
    const int d = __ldg(&g_degi[n]);

    float4 acc = *(const float4*)(P + (long)n * INC + l8 * 4);  // self
    int i = 0;
    for (; i + 4 <= d; i += 4) {
        const int s0 = __ldg(&g_csr[o + i]);
        const int s1 = __ldg(&g_csr[o + i + 1]);
        const int s2 = __ldg(&g_csr[o + i + 2]);
        const int s3 = __ldg(&g_csr[o + i + 3]);
        const float4 v0 = *(const float4*)(P + (long)s0 * INC + l8 * 4);
        const float4 v1 = *(const float4*)(P + (long)s1 * INC + l8 * 4);
        const float4 v2 = *(const float4*)(P + (long)s2 * INC + l8 * 4);
        const float4 v3 = *(const float4*)(P + (long)s3 * INC + l8 * 4);
        acc.x += (v0.x + v1.x) + (v2.x + v3.x);
        acc.y += (v0.y + v1.y) + (v2.y + v3.y);
        acc.z += (v0.z + v1.z) + (v2.z + v3.z);
        acc.w += (v0.w + v1.w) + (v2.w + v3.w);
    }
    for (; i < d; i++) {
        const int s = __ldg(&g_csr[o + i]);
        const float4 v = *(const float4*)(P + (long)s * INC + l8 * 4);
        acc.x += v.x; acc.y += v.y; acc.z += v.z; acc.w += v.w;
    }
    const float dn = __ldg(&g_dinv[n]);
    const float4 b4 = __ldg(&((const float4*)b)[l8]);
    float4 r;
    r.x = fmaf(acc.x, dn, b4.x); r.y = fmaf(acc.y, dn, b4.y);
    r.z = fmaf(acc.z, dn, b4.z); r.w = fmaf(acc.w, dn, b4.w);
    *(float4*)(out + (long)n * INC + l8 * 4) = r;
}

// ------------------------------------------------------------------
// GEMM: register-blocked 4 nodes x 8 channels per thread. blockDim=256.
// MODE 0: out = in@W + b                  (fp32)
// MODE 1: payload = (in@W)*dinv  fp32     (for fp32 gathers)
// MODE 2: payload = (in@W)*dinv  fp16     (packed half rows)
// ------------------------------------------------------------------
template <int KIN, int COUT, bool RELUIN, int MODE>
__global__ void __launch_bounds__(256, 3)
k_gemm(const float* __restrict__ in,
       const float* __restrict__ W,
       const float* __restrict__ b,
       float* __restrict__ dst) {
    constexpr int TPN = COUT / 8;
    constexpr int NG  = 256 / TPN;
    constexpr int NPB = NG * 4;
    constexpr int XSS = KIN + 1;

    __shared__ float Ws[KIN * COUT];
    __shared__ float bs[COUT];
    __shared__ float xs[NPB * XSS];

    const int tid = threadIdx.x;
    const int n0 = blockIdx.x * NPB;

    {
        const float4* W4 = (const float4*)W;
        float4* Ws4 = (float4*)Ws;
#pragma unroll
        for (int i = tid; i < KIN * COUT / 4; i += 256) Ws4[i] = W4[i];
    }
    if (tid < COUT) bs[tid] = (MODE == 0) ? b[tid] : 0.f;

    {
        constexpr int QPR = KIN / 4;
        constexpr int NQ = NPB * QPR;
        for (int i = tid; i < NQ; i += 256) {
            const int row = i / QPR;
            const int qc = i % QPR;
            float4 v = make_float4(0.f, 0.f, 0.f, 0.f);
            if (n0 + row < NN) {
                v = *(const float4*)(in + (long)(n0 + row) * KIN + qc * 4);
                if (RELUIN) {
                    v.x = fmaxf(v.x, 0.f); v.y = fmaxf(v.y, 0.f);
                    v.z = fmaxf(v.z, 0.f); v.w = fmaxf(v.w, 0.f);
                }
            }
            float* p = xs + row * XSS + qc * 4;
            p[0] = v.x; p[1] = v.y; p[2] = v.z; p[3] = v.w;
        }
    }
    __syncthreads();

    const int tc = tid % TPN;
    const int ng = tid / TPN;
    const int c0 = tc * 8;
    const int nb = ng * 4;

    float acc[4][8];
#pragma unroll
    for (int j = 0; j < 4; j++)
#pragma unroll
        for (int m = 0; m < 8; m++) acc[j][m] = 0.f;

    const float4* Ws4 = (const float4*)Ws;
#pragma unroll 8
    for (int k = 0; k < KIN; k++) {
        const float4 w0 = Ws4[(k * COUT + c0) >> 2];
        const float4 w1 = Ws4[((k * COUT + c0) >> 2) + 1];
        float xv[4];
#pragma unroll
        for (int j = 0; j < 4; j++) xv[j] = xs[(nb + j) * XSS + k];
#pragma unroll
        for (int j = 0; j < 4; j++) {
            acc[j][0] = fmaf(xv[j], w0.x, acc[j][0]);
            acc[j][1] = fmaf(xv[j], w0.y, acc[j][1]);
            acc[j][2] = fmaf(xv[j], w0.z, acc[j][2]);
            acc[j][3] = fmaf(xv[j], w0.w, acc[j][3]);
            acc[j][4] = fmaf(xv[j], w1.x, acc[j][4]);
            acc[j][5] = fmaf(xv[j], w1.y, acc[j][5]);
            acc[j][6] = fmaf(xv[j], w1.z, acc[j][6]);
            acc[j][7] = fmaf(xv[j], w1.w, acc[j][7]);
        }
    }

#pragma unroll
    for (int j = 0; j < 4; j++) {
        const int n = n0 + nb + j;
        if (n >= NN) break;
        if (MODE == 2) {
            const float d = g_dinv[n];
            union { uint4 u; __half2 h[4]; } pk;
            pk.h[0] = __floats2half2_rn(acc[j][0] * d, acc[j][1] * d);
            pk.h[1] = __floats2half2_rn(acc[j][2] * d, acc[j][3] * d);
            pk.h[2] = __floats2half2_rn(acc[j][4] * d, acc[j][5] * d);
            pk.h[3] = __floats2half2_rn(acc[j][6] * d, acc[j][7] * d);
            *(uint4*)((__half*)dst + (long)n * COUT + c0) = pk.u;
        } else if (MODE == 1) {
            const float d = g_dinv[n];
            float4 o0, o1;
            o0.x = acc[j][0] * d; o0.y = acc[j][1] * d;
            o0.z = acc[j][2] * d; o0.w = acc[j][3] * d;
            o1.x = acc[j][4] * d; o1.y = acc[j][5] * d;
            o1.z = acc[j][6] * d; o1.w = acc[j][7] * d;
            float* op = dst + (long)n * COUT + c0;
            *(float4*)(op) = o0; *(float4*)(op + 4) = o1;
        } else {
            float4 o0, o1;
            o0.x = acc[j][0] + bs[c0 + 0]; o0.y = acc[j][1] + bs[c0 + 1];
            o0.z = acc[j][2] + bs[c0 + 2]; o0.w = acc[j][3] + bs[c0 + 3];
            o1.x = acc[j][4] + bs[c0 + 4]; o1.y = acc[j][5] + bs[c0 + 5];
            o1.z = acc[j][6] + bs[c0 + 6]; o1.w = acc[j][7] + bs[c0 + 7];
            float* op = dst + (long)n * COUT + c0;
            *(float4*)(op) = o0; *(float4*)(op + 4) = o1;
        }
    }
}

// ------------------------------------------------------------------
// Pool: register run-length accumulation over sorted batch ids.
// ------------------------------------------------------------------
__global__ void k_pool(const int* __restrict__ batch, const float* __restrict__ h) {
    const int tid = threadIdx.x;
    const int c = tid % HC;
    const int r = tid / HC;
    float acc = 0.f;
    float cacc = 0.f;
    int curg = -1;
    for (int n = blockIdx.x * 4 + r; n < NN; n += gridDim.x * 4) {
        const int g = __ldg(&batch[n]);
        if (g != curg) {
            if (curg >= 0) {
                atomicAdd(&g_sums[curg * HC + c], acc);
                if (c == 0) atomicAdd(&g_cnt[curg], cacc);
            }
            acc = 0.f; cacc = 0.f; curg = g;
        }
        acc += fmaxf(h[(long)n * HC + c], 0.f);
        cacc += 1.f;
    }
    if (curg >= 0) {
        atomicAdd(&g_sums[curg * HC + c], acc);
        if (c == 0) atomicAdd(&g_cnt[curg], cacc);
    }
}

// ------------------------------------------------------------------
// Fused latent path: z = (sums/cnt)@Wp + bp  (also to d_out);
// D = relu(z@Wdp + bdp); XW = D @ W_dec0.   One block of 1024.
// ------------------------------------------------------------------
__global__ void __launch_bounds__(1024)
k_latent(const float* __restrict__ Wp, const float* __restrict__ bp,
         const float* __restrict__ Wdp, const float* __restrict__ bdp,
         const float* __restrict__ Wd0, float* __restrict__ zout) {
    __shared__ float zs[GG * LC];
    __shared__ float Ds[GG * HC];
    __shared__ float Wd0s[HC * HC];
    const int tid = threadIdx.x;        // 0..1023 = GG*LC exactly

    // z projection
    {
        const int g = tid / LC, l = tid % LC;
        const float inv = 1.0f / fmaxf(g_cnt[g], 1.0f);
        float s = bp[l];
#pragma unroll
        for (int k = 0; k < HC; k++)
            s = fmaf(g_sums[g * HC + k] * inv, Wp[k * LC + l], s);
        zs[g * LC + l] = s;
        zout[g * LC + l] = s;
    }
    for (int i = tid; i < HC * HC; i += 1024) Wd0s[i] = Wd0[i];
    __syncthreads();

    // D = relu(z @ Wdp + bdp)
    for (int i = tid; i < GG * HC; i += 1024) {
        const int g = i / HC, c = i % HC;
        float s = bdp[c];
#pragma unroll
        for (int k = 0; k < LC; k++) s = fmaf(zs[g * LC + k], Wdp[k * HC + c], s);
        Ds[i] = fmaxf(s, 0.f);
    }
    __syncthreads();

    // XW = D @ Wd0
    for (int i = tid; i < GG * HC; i += 1024) {
        const int g = i / HC, c = i % HC;
        float s = 0.f;
#pragma unroll 16
        for (int k = 0; k < HC; k++) s = fmaf(Ds[g * HC + k], Wd0s[k * HC + c], s);
        g_XW[i] = s;
    }
}

// ------------------------------------------------------------------
extern "C" void kernel_launch(void* const* d_in, const int* in_sizes, int n_in,
                              void* d_out, int out_size) {
    const float* x       = (const float*)d_in[0];
    const int*   ei      = (const int*)  d_in[1];
    const int*   batch   = (const int*)  d_in[2];
    const float* W_enc0  = (const float*)d_in[3];
    const float* b_enc0  = (const float*)d_in[4];
    const float* W_enc1  = (const float*)d_in[5];
    const float* b_enc1  = (const float*)d_in[6];
    const float* W_enc2  = (const float*)d_in[7];
    const float* b_enc2  = (const float*)d_in[8];
    const float* W_proj  = (const float*)d_in[9];
    const float* b_proj  = (const float*)d_in[10];
    const float* W_decp  = (const float*)d_in[11];
    const float* b_decp  = (const float*)d_in[12];
    const float* W_dec0  = (const float*)d_in[13];
    const float* b_dec0  = (const float*)d_in[14];
    const float* W_dec1  = (const float*)d_in[15];
    const float* b_dec1  = (const float*)d_in[16];

    float* out  = (float*)d_out;
    float* xrec = out;             // [NN, INC]
    float* zout = out + NN * INC;  // [GG, LC]

    float *p_xws, *p_buf0, *p_buf1;
    cudaGetSymbolAddress((void**)&p_xws,  g_xws);
    cudaGetSymbolAddress((void**)&p_buf0, g_buf0);
    cudaGetSymbolAddress((void**)&p_buf1, g_buf1);

    const int TB = 256;
    const int gN    = (NN + TB - 1) / TB;
    const int gE    = (EE + TB - 1) / TB;
    const int gA64  = (NN + 127) / 128;     // GEMM COUT=64
    const int gA32  = (NN + 255) / 256;     // GEMM COUT=32
    const int gG64  = (NN + 15) / 16;       // gather_tab: 16 nodes/block
    const int gG32  = (NN + 31) / 32;       // quarter-warp gathers: 32 nodes/block

    // ---- degree, CSR build, dinv ----
    k_init<<<gN, TB>>>();
    k_count<<<gE, TB>>>(ei);
    k_scan1<<<NB1, 1024>>>();
    k_scan3<<<NB1, 1024>>>();
    k_fill<<<gE, TB>>>(ei);

    // ---- conv0 (fused aggregate in input space, then GEMM) ----
    k_gather32x<<<gG32, TB>>>(x, p_buf1);
    k_gemm<INC, HC, false, 0><<<gA64, TB>>>(p_buf1, W_enc0, b_enc0, p_buf0);

    // ---- conv1 (fp16 payload) ----
    k_gemm<HC, HC, true, 2><<<gA64, TB>>>(p_buf0, W_enc1, nullptr, p_xws);
    k_gather64h<<<gG32, TB>>>((const __half*)p_xws, b_enc1, p_buf1);
    // ---- conv2 (fp16 payload) ----
    k_gemm<HC, HC, true, 2><<<gA64, TB>>>(p_buf1, W_enc2, nullptr, p_xws);
    k_gather64h<<<gG32, TB>>>((const __half*)p_xws, b_enc2, p_buf0);

    // ---- pool + fused latent/decoder head ----
    k_pool<<<592, TB>>>(batch, p_buf0);
    k_latent<<<1, 1024>>>(W_proj, b_proj, W_decp, b_decp, W_dec0, zout);

    // ---- dec conv0 via graph table (gather, no N-wide GEMM) ----
    k_gather_tab<<<gG64, TB>>>(batch, b_dec0, p_buf1);

    // ---- dec conv1 (fp32 payload for output accuracy) ----
    k_gemm<HC, INC, true, 1><<<gA32, TB>>>(p_buf1, W_dec1, nullptr, p_xws);
    k_gather32p<<<gG32, TB>>>(p_xws, b_dec1, xrec);
}